// round 9
// baseline (speedup 1.0000x reference)
#include <cuda_runtime.h>
#include <math.h>

// Problem constants
#define BATCH 16
#define CH    256          // channels per input feature map
#define CC    512          // concatenated channels
#define HW    1024         // 32*32 spatial
#define KDIM  (CC * 9)     // 4608, im2col reduction dim
#define CO    256          // output channels of final 1x1 conv

// ---------------- scratch (device globals: allocation-free) ----------------
__device__ float g_xcat  [BATCH * CC * HW];          //  33.5 MB  concat(x1,x2)
__device__ float g_im2col[(size_t)BATCH * KDIM * HW];// 302   MB  im2col of xcat
__device__ float g_value [BATCH * CC * HW];          //  33.5 MB  conv3x3 result
__device__ float g_attn  [BATCH * CC * CC];          //  16.8 MB  sim -> attn (in place)
__device__ float g_rmap  [CC * CC];                  //   1   MB  weight1 @ weight2^T
__device__ float g_T     [BATCH * CO * CC];          //   8.4 MB  w_w @ attn

// ---------------- f32x2 helpers (Blackwell packed fp32 FMA) ----------------
__device__ __forceinline__ unsigned long long pack2f(float lo, float hi) {
    unsigned long long r;
    asm("mov.b64 %0, {%1, %2};" : "=l"(r) : "f"(lo), "f"(hi));
    return r;
}
__device__ __forceinline__ void unpack2f(unsigned long long v, float& lo, float& hi) {
    asm("mov.b64 {%0, %1}, %2;" : "=f"(lo), "=f"(hi) : "l"(v));
}
__device__ __forceinline__ void ffma2(unsigned long long& d,
                                      unsigned long long a,
                                      unsigned long long b) {
    asm("fma.rn.f32x2 %0, %1, %2, %0;" : "+l"(d) : "l"(a), "l"(b));
}

// ---------------- concat: xcat[b][c][n] = (c<256 ? x1 : x2) ----------------
__global__ void concat_kernel(const float4* __restrict__ x1,
                              const float4* __restrict__ x2,
                              float4* __restrict__ xc) {
    const int n4 = HW / 4;                       // 256 float4 per channel image
    int idx = blockIdx.x * 256 + threadIdx.x;    // total BATCH*CC*n4 = 2,097,152
    int p = idx % n4;
    int c = (idx / n4) % CC;
    int b = idx / (n4 * CC);
    xc[idx] = (c < CH) ? x1[(b * CH + c) * n4 + p]
                       : x2[(b * CH + (c - CH)) * n4 + p];
}

// ---------------- im2col for 3x3 SAME conv on 32x32 ----------------
__global__ void im2col_kernel(const float* __restrict__ xc,
                              float* __restrict__ im) {
    int idx = blockIdx.x * 256 + threadIdx.x;    // total BATCH*KDIM*HW = 75,497,472
    int p = idx & 1023;
    int r = idx >> 10;                           // b*KDIM + k
    int k = r % KDIM;
    int b = r / KDIM;
    int ci = k / 9, t = k % 9;
    int ky = t / 3, kx = t % 3;
    int y = (p >> 5) + ky - 1;
    int x = (p & 31) + kx - 1;
    float v = 0.f;
    if ((unsigned)y < 32u && (unsigned)x < 32u)
        v = xc[(((long)(b * CC + ci)) << 10) + (y << 5) + x];
    im[idx] = v;
}

// ---------------- random_map = weight1 @ weight2^T  [512,512], K=16 --------
__global__ void rmap_kernel(const float* __restrict__ w1,
                            const float* __restrict__ w2,
                            float* __restrict__ rm) {
    int idx = blockIdx.x * 256 + threadIdx.x;    // 512*512
    int i = idx >> 9, j = idx & 511;
    float s = 0.f;
#pragma unroll
    for (int k = 0; k < 16; k++) s += w1[i * 16 + k] * w2[j * 16 + k];
    rm[idx] = s;
}

// ---------------- batched SGEMM: C = alpha * A @ (BT ? B^T : B) ------------
// A [M,K] row-major, B [K,N] (NN) or [N,K] (NT) row-major, C [M,N] row-major.
// Tile 128x128x8, 256 threads, 8x8 microtile, f32x2 accumulators.
// Requires: M,N multiples of 128; K multiple of 8. All call sites satisfy this.
template <bool BT>
__global__ __launch_bounds__(256)
void sgemm_kernel(const float* __restrict__ Ag, const float* __restrict__ Bg,
                  float* __restrict__ Cg, int M, int N, int K,
                  long strideA, long strideB, long strideC, float alpha) {
    __shared__ float As[8][128];   // k-major (transposed A tile)
    __shared__ float Bs[8][128];   // k-major
    const float* A = Ag + (long)blockIdx.z * strideA;
    const float* B = Bg + (long)blockIdx.z * strideB;
    float*       C = Cg + (long)blockIdx.z * strideC;
    const int bm = blockIdx.y * 128;
    const int bn = blockIdx.x * 128;
    const int tid = threadIdx.x;
    const int tx = tid & 15, ty = tid >> 4;
    const int lr  = tid >> 1;            // 0..127 (load row for A / transposed B)
    const int lc  = (tid & 1) * 4;       // 0 or 4 (k sub-offset)
    const int bnr = tid >> 5;            // 0..7   (NN B k-row)
    const int bnc = (tid & 31) * 4;      // 0..124 (NN B n-col)

    unsigned long long acc[8][4];
#pragma unroll
    for (int i = 0; i < 8; i++)
#pragma unroll
        for (int j = 0; j < 4; j++) acc[i][j] = 0ull;

    for (int kt = 0; kt < K; kt += 8) {
        float4 av = *(const float4*)(A + (long)(bm + lr) * K + kt + lc);
        float4 bv;
        if (BT) bv = *(const float4*)(B + (long)(bn + lr) * K + kt + lc);
        else    bv = *(const float4*)(B + (long)(kt + bnr) * N + bn + bnc);
        __syncthreads();
        As[lc + 0][lr] = av.x; As[lc + 1][lr] = av.y;
        As[lc + 2][lr] = av.z; As[lc + 3][lr] = av.w;
        if (BT) {
            Bs[lc + 0][lr] = bv.x; Bs[lc + 1][lr] = bv.y;
            Bs[lc + 2][lr] = bv.z; Bs[lc + 3][lr] = bv.w;
        } else {
            *(float4*)&Bs[bnr][bnc] = bv;
        }
        __syncthreads();
#pragma unroll
        for (int k = 0; k < 8; k++) {
            float4 a0 = *(const float4*)&As[k][ty * 8];
            float4 a1 = *(const float4*)&As[k][ty * 8 + 4];
            float4 b0 = *(const float4*)&Bs[k][tx * 8];
            float4 b1 = *(const float4*)&Bs[k][tx * 8 + 4];
            unsigned long long bb0 = pack2f(b0.x, b0.y);
            unsigned long long bb1 = pack2f(b0.z, b0.w);
            unsigned long long bb2 = pack2f(b1.x, b1.y);
            unsigned long long bb3 = pack2f(b1.z, b1.w);
            float a[8] = {a0.x, a0.y, a0.z, a0.w, a1.x, a1.y, a1.z, a1.w};
#pragma unroll
            for (int i = 0; i < 8; i++) {
                unsigned long long aa = pack2f(a[i], a[i]);
                ffma2(acc[i][0], aa, bb0);
                ffma2(acc[i][1], aa, bb1);
                ffma2(acc[i][2], aa, bb2);
                ffma2(acc[i][3], aa, bb3);
            }
        }
    }
#pragma unroll
    for (int i = 0; i < 8; i++) {
        float o[8];
#pragma unroll
        for (int j = 0; j < 4; j++) unpack2f(acc[i][j], o[2 * j], o[2 * j + 1]);
        float* cp = C + (long)(bm + ty * 8 + i) * N + bn + tx * 8;
        float4 v0 = make_float4(alpha * o[0], alpha * o[1], alpha * o[2], alpha * o[3]);
        float4 v1 = make_float4(alpha * o[4], alpha * o[5], alpha * o[6], alpha * o[7]);
        *(float4*)cp = v0;
        *(float4*)(cp + 4) = v1;
    }
}

// ---------------- row softmax over 512, with random_map added --------------
__global__ void softmax_kernel(float* __restrict__ S, const float* __restrict__ rmap) {
    const int c = blockIdx.x, b = blockIdx.y;
    float* row = S + ((long)b * CC + c) * CC;
    const float* rm = rmap + (long)c * CC;
    const int t = threadIdx.x;               // 128 threads, 4 elems each
    __shared__ float smax[4], ssum[4];
    float v[4];
#pragma unroll
    for (int j = 0; j < 4; j++) v[j] = row[t + 128 * j] + rm[t + 128 * j];
    float m = fmaxf(fmaxf(v[0], v[1]), fmaxf(v[2], v[3]));
    for (int o = 16; o; o >>= 1) m = fmaxf(m, __shfl_xor_sync(0xffffffffu, m, o));
    if ((t & 31) == 0) smax[t >> 5] = m;
    __syncthreads();
    m = fmaxf(fmaxf(smax[0], smax[1]), fmaxf(smax[2], smax[3]));
    float e[4], s = 0.f;
#pragma unroll
    for (int j = 0; j < 4; j++) { e[j] = __expf(v[j] - m); s += e[j]; }
    for (int o = 16; o; o >>= 1) s += __shfl_xor_sync(0xffffffffu, s, o);
    if ((t & 31) == 0) ssum[t >> 5] = s;
    __syncthreads();
    s = ssum[0] + ssum[1] + ssum[2] + ssum[3];
    float inv = 1.0f / s;
#pragma unroll
    for (int j = 0; j < 4; j++) row[t + 128 * j] = e[j] * inv;
}

// ---------------- launch -----------------------------------------------------
extern "C" void kernel_launch(void* const* d_in, const int* in_sizes, int n_in,
                              void* d_out, int out_size) {
    const float* x1  = (const float*)d_in[0];   // [16,256,32,32]
    const float* x2  = (const float*)d_in[1];   // [16,256,32,32]
    const float* g_w = (const float*)d_in[2];   // [512,512,3,3] == [512,4608]
    const float* w_w = (const float*)d_in[3];   // [256,512,1,1] == [256,512]
    const float* w1  = (const float*)d_in[4];   // [512,16]
    const float* w2  = (const float*)d_in[5];   // [512,16]
    float* out = (float*)d_out;                 // [16,256,32,32]

    float *xcat, *im, *value, *attn, *rmap, *T;
    cudaGetSymbolAddress((void**)&xcat,  g_xcat);
    cudaGetSymbolAddress((void**)&im,    g_im2col);
    cudaGetSymbolAddress((void**)&value, g_value);
    cudaGetSymbolAddress((void**)&attn,  g_attn);
    cudaGetSymbolAddress((void**)&rmap,  g_rmap);
    cudaGetSymbolAddress((void**)&T,     g_T);

    // 1. concat x = [x1; x2]
    concat_kernel<<<(BATCH * CC * (HW / 4)) / 256, 256>>>(
        (const float4*)x1, (const float4*)x2, (float4*)xcat);

    // 2. im2col for the 3x3 SAME conv
    im2col_kernel<<<(int)(((long)BATCH * KDIM * HW) / 256), 256>>>(xcat, im);

    // 3. value = g_w @ im2col(x)   [512,4608] x [4608,1024], batched over b (A shared)
    {
        dim3 grid(HW / 128, CC / 128, BATCH);
        sgemm_kernel<false><<<grid, 256>>>(g_w, im, value, CC, HW, KDIM,
                                           0L, (long)KDIM * HW, (long)CC * HW, 1.0f);
    }

    // 4. random_map = weight1 @ weight2^T
    rmap_kernel<<<(CC * CC) / 256, 256>>>(w1, w2, rmap);

    // 5. sim = (q @ q^T) * c^-0.5    (NT GEMM, A == B == xcat[b])
    {
        dim3 grid(CC / 128, CC / 128, BATCH);
        float alpha = 1.0f / sqrtf((float)CC);
        sgemm_kernel<true><<<grid, 256>>>(xcat, xcat, attn, CC, CC, HW,
                                          (long)CC * HW, (long)CC * HW,
                                          (long)CC * CC, alpha);
    }

    // 6. attn = softmax(sim + random_map) row-wise, in place
    {
        dim3 grid(CC, BATCH);
        softmax_kernel<<<grid, 128>>>(attn, rmap);
    }

    // 7. T = w_w @ attn   [256,512] x [512,512]   (fold 1x1 conv before context)
    {
        dim3 grid(CC / 128, CO / 128, BATCH);
        sgemm_kernel<false><<<grid, 256>>>(w_w, attn, T, CO, CC, CC,
                                           0L, (long)CC * CC, (long)CO * CC, 1.0f);
    }

    // 8. out = T @ value   [256,512] x [512,1024]
    {
        dim3 grid(HW / 128, CO / 128, BATCH);
        sgemm_kernel<false><<<grid, 256>>>(T, value, out, CO, HW, CC,
                                           (long)CO * CC, (long)CC * HW,
                                           (long)CO * HW, 1.0f);
    }
}

// round 10
// speedup vs baseline: 1.0029x; 1.0029x over previous
#include <cuda_runtime.h>
#include <math.h>

// Problem constants
#define BATCH 16
#define CH    256          // channels per input feature map
#define CC    512          // concatenated channels
#define HW    1024         // 32*32 spatial
#define KDIM  (CC * 9)     // 4608, im2col reduction dim
#define CO    256          // output channels of final 1x1 conv

// ---------------- scratch (device globals: allocation-free) ----------------
__device__ float g_xcat  [BATCH * CC * HW];          //  33.5 MB  concat(x1,x2)
__device__ float g_im2col[(size_t)BATCH * KDIM * HW];// 302   MB  im2col of xcat
__device__ float g_value [BATCH * CC * HW];          //  33.5 MB  conv3x3 result
__device__ float g_attn  [BATCH * CC * CC];          //  16.8 MB  sim -> attn (in place)
__device__ float g_rmap  [CC * CC];                  //   1   MB  weight1 @ weight2^T
__device__ float g_T     [BATCH * CO * CC];          //   8.4 MB  w_w @ attn

// ---------------- f32x2 helpers (Blackwell packed fp32 FMA) ----------------
__device__ __forceinline__ unsigned long long pack2f(float lo, float hi) {
    unsigned long long r;
    asm("mov.b64 %0, {%1, %2};" : "=l"(r) : "f"(lo), "f"(hi));
    return r;
}
__device__ __forceinline__ void unpack2f(unsigned long long v, float& lo, float& hi) {
    asm("mov.b64 {%0, %1}, %2;" : "=f"(lo), "=f"(hi) : "l"(v));
}
__device__ __forceinline__ void ffma2(unsigned long long& d,
                                      unsigned long long a,
                                      unsigned long long b) {
    asm("fma.rn.f32x2 %0, %1, %2, %0;" : "+l"(d) : "l"(a), "l"(b));
}

// ---------------- concat: xcat[b][c][n] = (c<256 ? x1 : x2) ----------------
__global__ void concat_kernel(const float4* __restrict__ x1,
                              const float4* __restrict__ x2,
                              float4* __restrict__ xc) {
    const int n4 = HW / 4;                       // 256 float4 per channel image
    int idx = blockIdx.x * 256 + threadIdx.x;    // total BATCH*CC*n4 = 2,097,152
    int p = idx % n4;
    int c = (idx / n4) % CC;
    int b = idx / (n4 * CC);
    xc[idx] = (c < CH) ? x1[(b * CH + c) * n4 + p]
                       : x2[(b * CH + (c - CH)) * n4 + p];
}

// ---------------- im2col for 3x3 SAME conv on 32x32 ----------------
__global__ void im2col_kernel(const float* __restrict__ xc,
                              float* __restrict__ im) {
    int idx = blockIdx.x * 256 + threadIdx.x;    // total BATCH*KDIM*HW = 75,497,472
    int p = idx & 1023;
    int r = idx >> 10;                           // b*KDIM + k
    int k = r % KDIM;
    int b = r / KDIM;
    int ci = k / 9, t = k % 9;
    int ky = t / 3, kx = t % 3;
    int y = (p >> 5) + ky - 1;
    int x = (p & 31) + kx - 1;
    float v = 0.f;
    if ((unsigned)y < 32u && (unsigned)x < 32u)
        v = xc[(((long)(b * CC + ci)) << 10) + (y << 5) + x];
    im[idx] = v;
}

// ---------------- random_map = weight1 @ weight2^T  [512,512], K=16 --------
__global__ void rmap_kernel(const float* __restrict__ w1,
                            const float* __restrict__ w2,
                            float* __restrict__ rm) {
    int idx = blockIdx.x * 256 + threadIdx.x;    // 512*512
    int i = idx >> 9, j = idx & 511;
    float s = 0.f;
#pragma unroll
    for (int k = 0; k < 16; k++) s += w1[i * 16 + k] * w2[j * 16 + k];
    rm[idx] = s;
}

// ---------------- batched SGEMM: C = alpha * A @ (BT ? B^T : B) ------------
// A [M,K] row-major, B [K,N] (NN) or [N,K] (NT) row-major, C [M,N] row-major.
// Tile 128x128x8, 256 threads, 8x8 microtile, f32x2 accumulators.
// Requires: M,N multiples of 128; K multiple of 8. All call sites satisfy this.
template <bool BT>
__global__ __launch_bounds__(256)
void sgemm_kernel(const float* __restrict__ Ag, const float* __restrict__ Bg,
                  float* __restrict__ Cg, int M, int N, int K,
                  long strideA, long strideB, long strideC, float alpha) {
    __shared__ float As[8][128];   // k-major (transposed A tile)
    __shared__ float Bs[8][128];   // k-major
    const float* A = Ag + (long)blockIdx.z * strideA;
    const float* B = Bg + (long)blockIdx.z * strideB;
    float*       C = Cg + (long)blockIdx.z * strideC;
    const int bm = blockIdx.y * 128;
    const int bn = blockIdx.x * 128;
    const int tid = threadIdx.x;
    const int tx = tid & 15, ty = tid >> 4;
    const int lr  = tid >> 1;            // 0..127 (load row for A / transposed B)
    const int lc  = (tid & 1) * 4;       // 0 or 4 (k sub-offset)
    const int bnr = tid >> 5;            // 0..7   (NN B k-row)
    const int bnc = (tid & 31) * 4;      // 0..124 (NN B n-col)

    unsigned long long acc[8][4];
#pragma unroll
    for (int i = 0; i < 8; i++)
#pragma unroll
        for (int j = 0; j < 4; j++) acc[i][j] = 0ull;

    for (int kt = 0; kt < K; kt += 8) {
        float4 av = *(const float4*)(A + (long)(bm + lr) * K + kt + lc);
        float4 bv;
        if (BT) bv = *(const float4*)(B + (long)(bn + lr) * K + kt + lc);
        else    bv = *(const float4*)(B + (long)(kt + bnr) * N + bn + bnc);
        __syncthreads();
        As[lc + 0][lr] = av.x; As[lc + 1][lr] = av.y;
        As[lc + 2][lr] = av.z; As[lc + 3][lr] = av.w;
        if (BT) {
            Bs[lc + 0][lr] = bv.x; Bs[lc + 1][lr] = bv.y;
            Bs[lc + 2][lr] = bv.z; Bs[lc + 3][lr] = bv.w;
        } else {
            *(float4*)&Bs[bnr][bnc] = bv;
        }
        __syncthreads();
#pragma unroll
        for (int k = 0; k < 8; k++) {
            float4 a0 = *(const float4*)&As[k][ty * 8];
            float4 a1 = *(const float4*)&As[k][ty * 8 + 4];
            float4 b0 = *(const float4*)&Bs[k][tx * 8];
            float4 b1 = *(const float4*)&Bs[k][tx * 8 + 4];
            unsigned long long bb0 = pack2f(b0.x, b0.y);
            unsigned long long bb1 = pack2f(b0.z, b0.w);
            unsigned long long bb2 = pack2f(b1.x, b1.y);
            unsigned long long bb3 = pack2f(b1.z, b1.w);
            float a[8] = {a0.x, a0.y, a0.z, a0.w, a1.x, a1.y, a1.z, a1.w};
#pragma unroll
            for (int i = 0; i < 8; i++) {
                unsigned long long aa = pack2f(a[i], a[i]);
                ffma2(acc[i][0], aa, bb0);
                ffma2(acc[i][1], aa, bb1);
                ffma2(acc[i][2], aa, bb2);
                ffma2(acc[i][3], aa, bb3);
            }
        }
    }
#pragma unroll
    for (int i = 0; i < 8; i++) {
        float o[8];
#pragma unroll
        for (int j = 0; j < 4; j++) unpack2f(acc[i][j], o[2 * j], o[2 * j + 1]);
        float* cp = C + (long)(bm + ty * 8 + i) * N + bn + tx * 8;
        float4 v0 = make_float4(alpha * o[0], alpha * o[1], alpha * o[2], alpha * o[3]);
        float4 v1 = make_float4(alpha * o[4], alpha * o[5], alpha * o[6], alpha * o[7]);
        *(float4*)cp = v0;
        *(float4*)(cp + 4) = v1;
    }
}

// ---------------- row softmax over 512, with random_map added --------------
__global__ void softmax_kernel(float* __restrict__ S, const float* __restrict__ rmap) {
    const int c = blockIdx.x, b = blockIdx.y;
    float* row = S + ((long)b * CC + c) * CC;
    const float* rm = rmap + (long)c * CC;
    const int t = threadIdx.x;               // 128 threads, 4 elems each
    __shared__ float smax[4], ssum[4];
    float v[4];
#pragma unroll
    for (int j = 0; j < 4; j++) v[j] = row[t + 128 * j] + rm[t + 128 * j];
    float m = fmaxf(fmaxf(v[0], v[1]), fmaxf(v[2], v[3]));
    for (int o = 16; o; o >>= 1) m = fmaxf(m, __shfl_xor_sync(0xffffffffu, m, o));
    if ((t & 31) == 0) smax[t >> 5] = m;
    __syncthreads();
    m = fmaxf(fmaxf(smax[0], smax[1]), fmaxf(smax[2], smax[3]));
    float e[4], s = 0.f;
#pragma unroll
    for (int j = 0; j < 4; j++) { e[j] = __expf(v[j] - m); s += e[j]; }
    for (int o = 16; o; o >>= 1) s += __shfl_xor_sync(0xffffffffu, s, o);
    if ((t & 31) == 0) ssum[t >> 5] = s;
    __syncthreads();
    s = ssum[0] + ssum[1] + ssum[2] + ssum[3];
    float inv = 1.0f / s;
#pragma unroll
    for (int j = 0; j < 4; j++) row[t + 128 * j] = e[j] * inv;
}

// ---------------- launch -----------------------------------------------------
extern "C" void kernel_launch(void* const* d_in, const int* in_sizes, int n_in,
                              void* d_out, int out_size) {
    const float* x1  = (const float*)d_in[0];   // [16,256,32,32]
    const float* x2  = (const float*)d_in[1];   // [16,256,32,32]
    const float* g_w = (const float*)d_in[2];   // [512,512,3,3] == [512,4608]
    const float* w_w = (const float*)d_in[3];   // [256,512,1,1] == [256,512]
    const float* w1  = (const float*)d_in[4];   // [512,16]
    const float* w2  = (const float*)d_in[5];   // [512,16]
    float* out = (float*)d_out;                 // [16,256,32,32]

    float *xcat, *im, *value, *attn, *rmap, *T;
    cudaGetSymbolAddress((void**)&xcat,  g_xcat);
    cudaGetSymbolAddress((void**)&im,    g_im2col);
    cudaGetSymbolAddress((void**)&value, g_value);
    cudaGetSymbolAddress((void**)&attn,  g_attn);
    cudaGetSymbolAddress((void**)&rmap,  g_rmap);
    cudaGetSymbolAddress((void**)&T,     g_T);

    // 1. concat x = [x1; x2]
    concat_kernel<<<(BATCH * CC * (HW / 4)) / 256, 256>>>(
        (const float4*)x1, (const float4*)x2, (float4*)xcat);

    // 2. im2col for the 3x3 SAME conv
    im2col_kernel<<<(int)(((long)BATCH * KDIM * HW) / 256), 256>>>(xcat, im);

    // 3. value = g_w @ im2col(x)   [512,4608] x [4608,1024], batched over b (A shared)
    {
        dim3 grid(HW / 128, CC / 128, BATCH);
        sgemm_kernel<false><<<grid, 256>>>(g_w, im, value, CC, HW, KDIM,
                                           0L, (long)KDIM * HW, (long)CC * HW, 1.0f);
    }

    // 4. random_map = weight1 @ weight2^T
    rmap_kernel<<<(CC * CC) / 256, 256>>>(w1, w2, rmap);

    // 5. sim = (q @ q^T) * c^-0.5    (NT GEMM, A == B == xcat[b])
    {
        dim3 grid(CC / 128, CC / 128, BATCH);
        float alpha = 1.0f / sqrtf((float)CC);
        sgemm_kernel<true><<<grid, 256>>>(xcat, xcat, attn, CC, CC, HW,
                                          (long)CC * HW, (long)CC * HW,
                                          (long)CC * CC, alpha);
    }

    // 6. attn = softmax(sim + random_map) row-wise, in place
    {
        dim3 grid(CC, BATCH);
        softmax_kernel<<<grid, 128>>>(attn, rmap);
    }

    // 7. T = w_w @ attn   [256,512] x [512,512]   (fold 1x1 conv before context)
    {
        dim3 grid(CC / 128, CO / 128, BATCH);
        sgemm_kernel<false><<<grid, 256>>>(w_w, attn, T, CO, CC, CC,
                                           0L, (long)CC * CC, (long)CO * CC, 1.0f);
    }

    // 8. out = T @ value   [256,512] x [512,1024]
    {
        dim3 grid(HW / 128, CO / 128, BATCH);
        sgemm_kernel<false><<<grid, 256>>>(T, value, out, CO, HW, CC,
                                           (long)CO * CC, (long)CC * HW,
                                           (long)CO * HW, 1.0f);
    }
}

// round 12
// speedup vs baseline: 1.3150x; 1.3113x over previous
#include <cuda_runtime.h>
#include <cuda_bf16.h>
#include <math.h>
#include <stdint.h>

// Problem constants
#define BATCH 16
#define CH    256          // channels per input feature map
#define CC    512          // concatenated channels
#define HW    1024         // 32*32 spatial
#define KDIM  (CC * 9)     // 4608, im2col reduction dim
#define CO    256          // output channels of final 1x1 conv

// ---------------- scratch (device globals: allocation-free) ----------------
__device__ float g_xcat  [BATCH * CC * HW];          //  33.5 MB  concat(x1,x2)
__device__ float g_value [BATCH * CC * HW];          //  33.5 MB  conv3x3 result
__device__ float g_attn  [BATCH * CC * CC];          //  16.8 MB  sim -> attn (in place)
__device__ float g_rmap  [CC * CC];                  //   1   MB  weight1 @ weight2^T
__device__ float g_T     [BATCH * CO * CC];          //   8.4 MB  w_w @ attn

__device__ __forceinline__ uint32_t smem_to_u32(const void* p) {
    uint32_t a;
    asm("{ .reg .u64 t; cvta.to.shared.u64 t, %1; cvt.u32.u64 %0, t; }"
        : "=r"(a) : "l"(p));
    return a;
}

// ---------------- warp-mma building blocks (sm_80+ instructions) -----------
#define LDSM_X4(R, ADDR) \
    asm volatile("ldmatrix.sync.aligned.m8n8.x4.shared.b16 {%0,%1,%2,%3}, [%4];" \
        : "=r"((R)[0]), "=r"((R)[1]), "=r"((R)[2]), "=r"((R)[3]) : "r"(ADDR))

#define MMA16816(D, A, B0, B1) \
    asm volatile("mma.sync.aligned.m16n8k16.row.col.f32.bf16.bf16.f32 " \
        "{%0,%1,%2,%3}, {%4,%5,%6,%7}, {%8,%9}, {%0,%1,%2,%3};" \
        : "+f"((D)[0]), "+f"((D)[1]), "+f"((D)[2]), "+f"((D)[3]) \
        : "r"((A)[0]), "r"((A)[1]), "r"((A)[2]), "r"((A)[3]), "r"(B0), "r"(B1))

// bf16 2-term split of a float pair -> packed hi / lo bf16x2 words
__device__ __forceinline__ void split2(float x, float y, uint32_t& hi, uint32_t& lo) {
    __nv_bfloat16 hx = __float2bfloat16(x), hy = __float2bfloat16(y);
    __nv_bfloat16 lx = __float2bfloat16(x - __bfloat162float(hx));
    __nv_bfloat16 ly = __float2bfloat16(y - __bfloat162float(hy));
    hi = ((uint32_t)__bfloat16_as_ushort(hy) << 16) | __bfloat16_as_ushort(hx);
    lo = ((uint32_t)__bfloat16_as_ushort(ly) << 16) | __bfloat16_as_ushort(lx);
}

// ================= conv3x3-as-GEMM via warp bf16 MMA, fused im2col =========
// value[b][m][n] = sum_k W[m][k] * im2col(xcat)[b][k][n]; M=512,N=1024,K=4608
// smem tiles: A[128 m][64 k], B[128 n][64 k], bf16 hi+lo, 128B rows,
// 16B-chunk XOR swizzle (chunk ^ (row&7)) -> conflict-free ldmatrix.
#define CONV_KC      64
#define CONV_CHUNKS  (KDIM / CONV_KC)      // 72
#define CTILE        16384                 // 128 rows x 128 bytes
#define CSTAGE       (4 * CTILE)           // Ah, Al, Bh, Bl = 64 KB
#define CONV_DSMEM   (1024 + 2 * CSTAGE)   // double buffered + align slack

__global__ __launch_bounds__(256, 1)
void conv_mma_kernel(const float* __restrict__ W,
                     const float* __restrict__ xcat,
                     float* __restrict__ out) {
    extern __shared__ char dsm_raw[];
    char* dsm = (char*)(((uintptr_t)dsm_raw + 1023) & ~(uintptr_t)1023);
    const uint32_t dsm_u32 = smem_to_u32(dsm);

    const int tid = threadIdx.x;
    const int wid = tid >> 5;
    const int lid = tid & 31;
    const int wm  = wid >> 2;            // 0..1 -> m offset 0/64
    const int wn  = wid & 3;             // 0..3 -> n offset 0/32/64/96
    const int m0  = wm * 64;
    const int n0  = wn * 32;

    const int bm = blockIdx.y * 128;     // output-channel tile
    const int bn = blockIdx.x * 128;     // spatial tile
    const int b  = blockIdx.z;
    const float* Wt = W + (long)bm * KDIM;
    const float* X  = xcat + (long)b * CC * HW;

    // fill roles: two threads per smem row, 32 k-elements each
    const int frow = tid >> 1;           // 0..127
    const int fhalf = tid & 1;           // 0 or 1 (k offset 0 / 32)

    float acc[4][4][4];
#pragma unroll
    for (int i = 0; i < 4; i++)
#pragma unroll
        for (int j = 0; j < 4; j++)
#pragma unroll
            for (int q = 0; q < 4; q++) acc[i][j][q] = 0.f;

    float4 fa[8];        // staged A floats (32)
    float  fb[32];       // staged B floats (gathered)

    // ---- stage loaders ----
    auto loadA = [&](int c) {
        const float* p = Wt + (long)frow * KDIM + c * CONV_KC + fhalf * 32;
#pragma unroll
        for (int j = 0; j < 8; j++) fa[j] = *(const float4*)(p + 4 * j);
    };
    auto loadB = [&](int c) {
        const int kb = c * CONV_KC + fhalf * 32;
        const int sp = bn + frow;
        const int y0 = sp >> 5, x0 = sp & 31;
#pragma unroll
        for (int kk = 0; kk < 32; kk++) {
            int kg = kb + kk;
            int ci = kg / 9;
            int r9 = kg - ci * 9;
            int ky = r9 / 3;
            int kx = r9 - ky * 3;
            int y = y0 + ky - 1, x = x0 + kx - 1;
            float v = 0.f;
            if ((unsigned)y < 32u && (unsigned)x < 32u)
                v = X[(ci << 10) + (y << 5) + x];
            fb[kk] = v;
        }
    };
    auto storeA = [&](int st) {
        char* sh = dsm + st * CSTAGE;            // A hi
        char* sl = sh + CTILE;                   // A lo
        const float* f = (const float*)fa;
#pragma unroll
        for (int j = 0; j < 4; j++) {
            uint4 hv, lv;
            split2(f[j*8+0], f[j*8+1], hv.x, lv.x);
            split2(f[j*8+2], f[j*8+3], hv.y, lv.y);
            split2(f[j*8+4], f[j*8+5], hv.z, lv.z);
            split2(f[j*8+6], f[j*8+7], hv.w, lv.w);
            int chunk = fhalf * 4 + j;
            uint32_t off = frow * 128 + (((chunk ^ (frow & 7))) << 4);
            *(uint4*)(sh + off) = hv;
            *(uint4*)(sl + off) = lv;
        }
    };
    auto storeB = [&](int st) {
        char* sh = dsm + st * CSTAGE + 2 * CTILE;   // B hi
        char* sl = sh + CTILE;                       // B lo
#pragma unroll
        for (int j = 0; j < 4; j++) {
            uint4 hv, lv;
            split2(fb[j*8+0], fb[j*8+1], hv.x, lv.x);
            split2(fb[j*8+2], fb[j*8+3], hv.y, lv.y);
            split2(fb[j*8+4], fb[j*8+5], hv.z, lv.z);
            split2(fb[j*8+6], fb[j*8+7], hv.w, lv.w);
            int chunk = fhalf * 4 + j;
            uint32_t off = frow * 128 + (((chunk ^ (frow & 7))) << 4);
            *(uint4*)(sh + off) = hv;
            *(uint4*)(sl + off) = lv;
        }
    };

    // ---- one k16 MMA step on stage st ----
    const int rsel = lid & 15, csel = lid >> 4;
    auto mma_step = [&](int st, int s) {
        const uint32_t base = dsm_u32 + st * CSTAGE;
        uint32_t ah[4][4], al[4][4], bh[2][4], bl[2][4];
#pragma unroll
        for (int am = 0; am < 4; am++) {
            int row = m0 + am * 16 + rsel;
            uint32_t off = row * 128 + ((((2 * s + csel) ^ (row & 7))) << 4);
            LDSM_X4(ah[am], base + off);
            LDSM_X4(al[am], base + CTILE + off);
        }
#pragma unroll
        for (int bi = 0; bi < 2; bi++) {
            int row = n0 + bi * 16 + rsel;
            uint32_t off = row * 128 + ((((2 * s + csel) ^ (row & 7))) << 4);
            LDSM_X4(bh[bi], base + 2 * CTILE + off);
            LDSM_X4(bl[bi], base + 3 * CTILE + off);
        }
#pragma unroll
        for (int am = 0; am < 4; am++)
#pragma unroll
            for (int g = 0; g < 4; g++) {
                int bi = g >> 1, u = g & 1;
                MMA16816(acc[am][g], ah[am], bh[bi][u], bh[bi][u + 2]);
                MMA16816(acc[am][g], ah[am], bl[bi][u], bl[bi][u + 2]);
                MMA16816(acc[am][g], al[am], bh[bi][u], bh[bi][u + 2]);
            }
    };

    // ---- pipelined main loop ----
    loadA(0); loadB(0);
    storeA(0); storeB(0);
    __syncthreads();

    for (int c = 0; c < CONV_CHUNKS; c++) {
        const int st = c & 1, ns = st ^ 1;
        const bool pf = (c + 1 < CONV_CHUNKS);
        if (pf) loadA(c + 1);
        mma_step(st, 0);
        mma_step(st, 1);
        if (pf) { storeA(ns); loadB(c + 1); }
        mma_step(st, 2);
        mma_step(st, 3);
        if (pf) storeB(ns);
        __syncthreads();
    }

    // ---- epilogue: acc -> value ----
    const int rg = lid >> 2;            // 0..7
    const int cg = (lid & 3) * 2;       // 0,2,4,6
#pragma unroll
    for (int am = 0; am < 4; am++)
#pragma unroll
        for (int g = 0; g < 4; g++) {
            int row = bm + m0 + am * 16 + rg;
            int col = bn + n0 + g * 8 + cg;
            float* p0 = out + (((long)b * CC + row) << 10) + col;
            *(float2*)p0 = make_float2(acc[am][g][0], acc[am][g][1]);
            float* p1 = p0 + (8 << 10);
            *(float2*)p1 = make_float2(acc[am][g][2], acc[am][g][3]);
        }
}

// ---------------- f32x2 helpers (packed fp32 FMA) --------------------------
__device__ __forceinline__ void ffma2(unsigned long long& d,
                                      unsigned long long a,
                                      unsigned long long b) {
    asm("fma.rn.f32x2 %0, %1, %2, %0;" : "+l"(d) : "l"(a), "l"(b));
}
__device__ __forceinline__ void unpack2f(unsigned long long v, float& lo, float& hi) {
    asm("mov.b64 {%0, %1}, %2;" : "=f"(lo), "=f"(hi) : "l"(v));
}

// ---------------- concat: xcat[b][c][n] = (c<256 ? x1 : x2) ----------------
__global__ void concat_kernel(const float4* __restrict__ x1,
                              const float4* __restrict__ x2,
                              float4* __restrict__ xc) {
    const int n4 = HW / 4;
    int idx = blockIdx.x * 256 + threadIdx.x;
    int p = idx % n4;
    int c = (idx / n4) % CC;
    int b = idx / (n4 * CC);
    xc[idx] = (c < CH) ? x1[(b * CH + c) * n4 + p]
                       : x2[(b * CH + (c - CH)) * n4 + p];
}

// ---------------- random_map = weight1 @ weight2^T  [512,512], K=16 --------
__global__ void rmap_kernel(const float* __restrict__ w1,
                            const float* __restrict__ w2,
                            float* __restrict__ rm) {
    int idx = blockIdx.x * 256 + threadIdx.x;
    int i = idx >> 9, j = idx & 511;
    float s = 0.f;
#pragma unroll
    for (int k = 0; k < 16; k++) s += w1[i * 16 + k] * w2[j * 16 + k];
    rm[idx] = s;
}

// ---------------- batched SGEMM (FFMA2, pack-free inner loop) --------------
// A [M,K] row-major, B [K,N] (NN) / [N,K] (NT) row-major, C [M,N] row-major.
template <bool BT>
__global__ __launch_bounds__(256)
void sgemm_kernel(const float* __restrict__ Ag, const float* __restrict__ Bg,
                  float* __restrict__ Cg, int M, int N, int K,
                  long strideA, long strideB, long strideC, float alpha) {
    __shared__ float2 Asd[8][128];   // A value duplicated per element -> LDS gives packed pair
    __shared__ float  Bs[8][128];    // k-major; adjacent n pairs read as u64
    const float* A = Ag + (long)blockIdx.z * strideA;
    const float* B = Bg + (long)blockIdx.z * strideB;
    float*       C = Cg + (long)blockIdx.z * strideC;
    const int bm = blockIdx.y * 128;
    const int bn = blockIdx.x * 128;
    const int tid = threadIdx.x;
    const int tx = tid & 15, ty = tid >> 4;
    const int lr  = tid >> 1;
    const int lc  = (tid & 1) * 4;
    const int bnr = tid >> 5;
    const int bnc = (tid & 31) * 4;

    unsigned long long acc[8][4];
#pragma unroll
    for (int i = 0; i < 8; i++)
#pragma unroll
        for (int j = 0; j < 4; j++) acc[i][j] = 0ull;

    for (int kt = 0; kt < K; kt += 8) {
        float4 av = *(const float4*)(A + (long)(bm + lr) * K + kt + lc);
        float4 bv;
        if (BT) bv = *(const float4*)(B + (long)(bn + lr) * K + kt + lc);
        else    bv = *(const float4*)(B + (long)(kt + bnr) * N + bn + bnc);
        __syncthreads();
        Asd[lc + 0][lr] = make_float2(av.x, av.x);
        Asd[lc + 1][lr] = make_float2(av.y, av.y);
        Asd[lc + 2][lr] = make_float2(av.z, av.z);
        Asd[lc + 3][lr] = make_float2(av.w, av.w);
        if (BT) {
            Bs[lc + 0][lr] = bv.x; Bs[lc + 1][lr] = bv.y;
            Bs[lc + 2][lr] = bv.z; Bs[lc + 3][lr] = bv.w;
        } else {
            *(float4*)&Bs[bnr][bnc] = bv;
        }
        __syncthreads();
#pragma unroll
        for (int k = 0; k < 8; k++) {
            const ulonglong2* ap = (const ulonglong2*)&Asd[k][ty * 8];
            ulonglong2 aA = ap[0], aB = ap[1], aC = ap[2], aD = ap[3];
            const ulonglong2* bp = (const ulonglong2*)&Bs[k][tx * 8];
            ulonglong2 bA = bp[0], bB = bp[1];
            unsigned long long aa[8] = {aA.x, aA.y, aB.x, aB.y,
                                        aC.x, aC.y, aD.x, aD.y};
            unsigned long long bb[4] = {bA.x, bA.y, bB.x, bB.y};
#pragma unroll
            for (int i = 0; i < 8; i++)
#pragma unroll
                for (int j = 0; j < 4; j++) ffma2(acc[i][j], aa[i], bb[j]);
        }
    }
#pragma unroll
    for (int i = 0; i < 8; i++) {
        float o[8];
#pragma unroll
        for (int j = 0; j < 4; j++) unpack2f(acc[i][j], o[2 * j], o[2 * j + 1]);
        float* cp = C + (long)(bm + ty * 8 + i) * N + bn + tx * 8;
        float4 v0 = make_float4(alpha * o[0], alpha * o[1], alpha * o[2], alpha * o[3]);
        float4 v1 = make_float4(alpha * o[4], alpha * o[5], alpha * o[6], alpha * o[7]);
        *(float4*)cp = v0;
        *(float4*)(cp + 4) = v1;
    }
}

// ---------------- row softmax over 512, with random_map added --------------
__global__ void softmax_kernel(float* __restrict__ S, const float* __restrict__ rmap) {
    const int c = blockIdx.x, b = blockIdx.y;
    float* row = S + ((long)b * CC + c) * CC;
    const float* rm = rmap + (long)c * CC;
    const int t = threadIdx.x;
    __shared__ float smax[4], ssum[4];
    float v[4];
#pragma unroll
    for (int j = 0; j < 4; j++) v[j] = row[t + 128 * j] + rm[t + 128 * j];
    float m = fmaxf(fmaxf(v[0], v[1]), fmaxf(v[2], v[3]));
    for (int o = 16; o; o >>= 1) m = fmaxf(m, __shfl_xor_sync(0xffffffffu, m, o));
    if ((t & 31) == 0) smax[t >> 5] = m;
    __syncthreads();
    m = fmaxf(fmaxf(smax[0], smax[1]), fmaxf(smax[2], smax[3]));
    float e[4], s = 0.f;
#pragma unroll
    for (int j = 0; j < 4; j++) { e[j] = __expf(v[j] - m); s += e[j]; }
    for (int o = 16; o; o >>= 1) s += __shfl_xor_sync(0xffffffffu, s, o);
    if ((t & 31) == 0) ssum[t >> 5] = s;
    __syncthreads();
    s = ssum[0] + ssum[1] + ssum[2] + ssum[3];
    float inv = 1.0f / s;
#pragma unroll
    for (int j = 0; j < 4; j++) row[t + 128 * j] = e[j] * inv;
}

// ---------------- launch ---------------------------------------------------
extern "C" void kernel_launch(void* const* d_in, const int* in_sizes, int n_in,
                              void* d_out, int out_size) {
    const float* x1  = (const float*)d_in[0];   // [16,256,32,32]
    const float* x2  = (const float*)d_in[1];   // [16,256,32,32]
    const float* g_w = (const float*)d_in[2];   // [512,512,3,3] == [512,4608]
    const float* w_w = (const float*)d_in[3];   // [256,512,1,1] == [256,512]
    const float* w1  = (const float*)d_in[4];   // [512,16]
    const float* w2  = (const float*)d_in[5];   // [512,16]
    float* out = (float*)d_out;                 // [16,256,32,32]

    float *xcat, *value, *attn, *rmap, *T;
    cudaGetSymbolAddress((void**)&xcat,  g_xcat);
    cudaGetSymbolAddress((void**)&value, g_value);
    cudaGetSymbolAddress((void**)&attn,  g_attn);
    cudaGetSymbolAddress((void**)&rmap,  g_rmap);
    cudaGetSymbolAddress((void**)&T,     g_T);

    cudaFuncSetAttribute(conv_mma_kernel,
                         cudaFuncAttributeMaxDynamicSharedMemorySize, CONV_DSMEM);

    // 1. concat x = [x1; x2]
    concat_kernel<<<(BATCH * CC * (HW / 4)) / 256, 256>>>(
        (const float4*)x1, (const float4*)x2, (float4*)xcat);

    // 2. value = conv3x3(x) via warp bf16-split MMA w/ fused im2col
    {
        dim3 grid(HW / 128, CC / 128, BATCH);   // (8, 4, 16)
        conv_mma_kernel<<<grid, 256, CONV_DSMEM>>>(g_w, xcat, value);
    }

    // 3. random_map = weight1 @ weight2^T
    rmap_kernel<<<(CC * CC) / 256, 256>>>(w1, w2, rmap);

    // 4. sim = (q @ q^T) * c^-0.5    (NT GEMM, fp32)
    {
        dim3 grid(CC / 128, CC / 128, BATCH);
        float alpha = 1.0f / sqrtf((float)CC);
        sgemm_kernel<true><<<grid, 256>>>(xcat, xcat, attn, CC, CC, HW,
                                          (long)CC * HW, (long)CC * HW,
                                          (long)CC * CC, alpha);
    }

    // 5. attn = softmax(sim + random_map) row-wise, in place
    {
        dim3 grid(CC, BATCH);
        softmax_kernel<<<grid, 128>>>(attn, rmap);
    }

    // 6. T = w_w @ attn   (fold 1x1 conv before context GEMM)
    {
        dim3 grid(CC / 128, CO / 128, BATCH);
        sgemm_kernel<false><<<grid, 256>>>(w_w, attn, T, CO, CC, CC,
                                           0L, (long)CC * CC, (long)CO * CC, 1.0f);
    }

    // 7. out = T @ value
    {
        dim3 grid(HW / 128, CO / 128, BATCH);
        sgemm_kernel<false><<<grid, 256>>>(T, value, out, CO, HW, CC,
                                           (long)CO * CC, (long)CC * HW,
                                           (long)CO * HW, 1.0f);
    }
}

// round 13
// speedup vs baseline: 1.5017x; 1.1419x over previous
#include <cuda_runtime.h>
#include <cuda_bf16.h>
#include <math.h>
#include <stdint.h>

// Problem constants
#define BATCH 16
#define CH    256
#define CC    512
#define HW    1024
#define KDIM  (CC * 9)     // 4608
#define CO    256

// ---------------- scratch (device globals: allocation-free) ----------------
__device__ __nv_bfloat16 g_xh[BATCH * CC * HW];               // 16.8 MB
__device__ __nv_bfloat16 g_xl[BATCH * CC * HW];               // 16.8 MB
__device__ __nv_bfloat16 g_wh[CC * KDIM];                     //  4.7 MB
__device__ __nv_bfloat16 g_wl[CC * KDIM];                     //  4.7 MB
__device__ __nv_bfloat16 g_bh[(size_t)BATCH * HW * KDIM];     //  151 MB  im2col^T hi
__device__ __nv_bfloat16 g_bl[(size_t)BATCH * HW * KDIM];     //  151 MB  im2col^T lo
__device__ float g_value[BATCH * CC * HW];                    // 33.5 MB
__device__ float g_attn [BATCH * CC * CC];                    // 16.8 MB
__device__ float g_rmap [CC * CC];
__device__ float g_T    [BATCH * CO * CC];

__device__ __forceinline__ uint32_t smem_to_u32(const void* p) {
    uint32_t a;
    asm("{ .reg .u64 t; cvta.to.shared.u64 t, %1; cvt.u32.u64 %0, t; }"
        : "=r"(a) : "l"(p));
    return a;
}

// ---------------- warp-mma building blocks (sm_80+ instructions) -----------
#define LDSM_X4(R, ADDR) \
    asm volatile("ldmatrix.sync.aligned.m8n8.x4.shared.b16 {%0,%1,%2,%3}, [%4];" \
        : "=r"((R)[0]), "=r"((R)[1]), "=r"((R)[2]), "=r"((R)[3]) : "r"(ADDR))

#define MMA16816(D, A, B0, B1) \
    asm volatile("mma.sync.aligned.m16n8k16.row.col.f32.bf16.bf16.f32 " \
        "{%0,%1,%2,%3}, {%4,%5,%6,%7}, {%8,%9}, {%0,%1,%2,%3};" \
        : "+f"((D)[0]), "+f"((D)[1]), "+f"((D)[2]), "+f"((D)[3]) \
        : "r"((A)[0]), "r"((A)[1]), "r"((A)[2]), "r"((A)[3]), "r"(B0), "r"(B1))

__device__ __forceinline__ void cp16(uint32_t s, const void* g) {
    asm volatile("cp.async.cg.shared.global [%0], [%1], 16;" :: "r"(s), "l"(g));
}
#define CP_COMMIT() asm volatile("cp.async.commit_group;" ::: "memory")
#define CP_WAIT1()  asm volatile("cp.async.wait_group 1;" ::: "memory")
#define CP_WAIT0()  asm volatile("cp.async.wait_group 0;" ::: "memory")

// bf16 2-term split of a float pair -> packed hi / lo bf16x2 words
__device__ __forceinline__ void split2(float x, float y, uint32_t& hi, uint32_t& lo) {
    __nv_bfloat16 hx = __float2bfloat16(x), hy = __float2bfloat16(y);
    __nv_bfloat16 lx = __float2bfloat16(x - __bfloat162float(hx));
    __nv_bfloat16 ly = __float2bfloat16(y - __bfloat162float(hy));
    hi = ((uint32_t)__bfloat16_as_ushort(hy) << 16) | __bfloat16_as_ushort(hx);
    lo = ((uint32_t)__bfloat16_as_ushort(ly) << 16) | __bfloat16_as_ushort(lx);
}

// ============ concat + bf16 split: x1,x2 -> Xh, Xl [b][c][sp] ==============
__global__ void concat_split_kernel(const float4* __restrict__ x1,
                                    const float4* __restrict__ x2,
                                    __nv_bfloat16* __restrict__ xh,
                                    __nv_bfloat16* __restrict__ xl) {
    int idx = blockIdx.x * 256 + threadIdx.x;     // 16*512*256 quads
    int p = idx & 255;
    int c = (idx >> 8) & 511;
    int b = idx >> 17;
    float4 v = (c < CH) ? x1[((b << 8) + c) * 256 + p]
                        : x2[((b << 8) + (c - CH)) * 256 + p];
    uint32_t h0, l0, h1, l1;
    split2(v.x, v.y, h0, l0);
    split2(v.z, v.w, h1, l1);
    *(uint2*)(xh + (size_t)idx * 4) = make_uint2(h0, h1);
    *(uint2*)(xl + (size_t)idx * 4) = make_uint2(l0, l1);
}

// ============ weight bf16 split: g_w -> Wh, Wl [m][k] ======================
__global__ void wsplit_kernel(const float4* __restrict__ w,
                              __nv_bfloat16* __restrict__ wh,
                              __nv_bfloat16* __restrict__ wl) {
    int idx = blockIdx.x * 256 + threadIdx.x;     // 512*4608/4 = 589824
    float4 v = w[idx];
    uint32_t h0, l0, h1, l1;
    split2(v.x, v.y, h0, l0);
    split2(v.z, v.w, h1, l1);
    *(uint2*)(wh + (size_t)idx * 4) = make_uint2(h0, h1);
    *(uint2*)(wl + (size_t)idx * 4) = make_uint2(l0, l1);
}

// ============ transposed im2col in bf16: Bh/Bl[b][n][k] ====================
__global__ void im2colT_kernel(const __nv_bfloat16* __restrict__ xh,
                               const __nv_bfloat16* __restrict__ xl,
                               __nv_bfloat16* __restrict__ bh,
                               __nv_bfloat16* __restrict__ bl) {
    int idx = blockIdx.x * 256 + threadIdx.x;     // 16*1024*576
    int g = idx % 576;
    int n = (idx / 576) & 1023;
    int b = idx / (576 * 1024);
    int k0 = g * 8;
    int ci = k0 / 9;
    int r9 = k0 - ci * 9;
    int y0 = n >> 5, x0 = n & 31;
    const unsigned short* Xh = (const unsigned short*)(xh + ((long)b << 19));
    const unsigned short* Xl = (const unsigned short*)(xl + ((long)b << 19));
    unsigned short hv[8], lv[8];
#pragma unroll
    for (int kk = 0; kk < 8; kk++) {
        int ky = (r9 >= 6) ? 2 : ((r9 >= 3) ? 1 : 0);
        int kx = r9 - ky * 3;
        int y = y0 + ky - 1, x = x0 + kx - 1;
        unsigned short h = 0, l = 0;
        if ((unsigned)y < 32u && (unsigned)x < 32u) {
            int o = (ci << 10) + (y << 5) + x;
            h = Xh[o]; l = Xl[o];
        }
        hv[kk] = h; lv[kk] = l;
        if (++r9 == 9) { r9 = 0; ci++; }
    }
    uint4 ph, pl;
    ph.x = hv[0] | ((uint32_t)hv[1] << 16); ph.y = hv[2] | ((uint32_t)hv[3] << 16);
    ph.z = hv[4] | ((uint32_t)hv[5] << 16); ph.w = hv[6] | ((uint32_t)hv[7] << 16);
    pl.x = lv[0] | ((uint32_t)lv[1] << 16); pl.y = lv[2] | ((uint32_t)lv[3] << 16);
    pl.z = lv[4] | ((uint32_t)lv[5] << 16); pl.w = lv[6] | ((uint32_t)lv[7] << 16);
    size_t base = (size_t)idx * 8;
    *(uint4*)((unsigned short*)bh + base) = ph;
    *(uint4*)((unsigned short*)bl + base) = pl;
}

// ============ generic NT HMMA GEMM, bf16 3-pass split, cp.async fills ======
// C[b][m][n] = alpha * sum_k (Ah+Al)[m][k] * (Bh+Bl)[n][k]   (lo*lo dropped)
// A,B K-major bf16; 128x128 CTA tile, K-chunk 64, double-buffered smem.
#define KC      64
#define HTILE   16384                 // 128 rows x 128 bytes (64 bf16)
#define HSTAGE  (4 * HTILE)           // Ah, Al, Bh, Bl
#define HDSMEM  (1024 + 2 * HSTAGE)

__global__ __launch_bounds__(256, 1)
void hmma_nt_kernel(const __nv_bfloat16* __restrict__ Ahg,
                    const __nv_bfloat16* __restrict__ Alg,
                    const __nv_bfloat16* __restrict__ Bhg,
                    const __nv_bfloat16* __restrict__ Blg,
                    float* __restrict__ Cg,
                    int M, int N, int K,
                    long sA, long sB, long sC, float alpha) {
    extern __shared__ char dsm_raw[];
    char* dsm = (char*)(((uintptr_t)dsm_raw + 1023) & ~(uintptr_t)1023);
    const uint32_t dsm_u32 = smem_to_u32(dsm);

    const int tid = threadIdx.x;
    const int wid = tid >> 5;
    const int lid = tid & 31;
    const int m0 = (wid >> 2) * 64;
    const int n0 = (wid & 3) * 32;
    const int bm = blockIdx.y * 128;
    const int bn = blockIdx.x * 128;
    const int b  = blockIdx.z;

    const __nv_bfloat16* Ah = Ahg + (long)b * sA;
    const __nv_bfloat16* Al = Alg + (long)b * sA;
    const __nv_bfloat16* Bh = Bhg + (long)b * sB;
    const __nv_bfloat16* Bl = Blg + (long)b * sB;
    float* C = Cg + (long)b * sC;

    const int frow = tid >> 1;       // 0..127
    const int fhalf = tid & 1;       // k offset 0 / 32

    float acc[4][4][4];
#pragma unroll
    for (int i = 0; i < 4; i++)
#pragma unroll
        for (int j = 0; j < 4; j++)
#pragma unroll
            for (int q = 0; q < 4; q++) acc[i][j][q] = 0.f;

    auto prefetch = [&](int c, int st) {
        const long kb = (long)c * KC + fhalf * 32;
        const uint32_t so = dsm_u32 + st * HSTAGE;
        const __nv_bfloat16* pAh = Ah + (long)(bm + frow) * K + kb;
        const __nv_bfloat16* pAl = Al + (long)(bm + frow) * K + kb;
        const __nv_bfloat16* pBh = Bh + (long)(bn + frow) * K + kb;
        const __nv_bfloat16* pBl = Bl + (long)(bn + frow) * K + kb;
#pragma unroll
        for (int j = 0; j < 4; j++) {
            int chunk = fhalf * 4 + j;
            uint32_t off = frow * 128 + (((chunk ^ (frow & 7))) << 4);
            cp16(so + off,              pAh + j * 8);
            cp16(so + HTILE + off,      pAl + j * 8);
            cp16(so + 2 * HTILE + off,  pBh + j * 8);
            cp16(so + 3 * HTILE + off,  pBl + j * 8);
        }
        CP_COMMIT();
    };

    const int rsel = lid & 15, csel = lid >> 4;
    auto mma_step = [&](int st, int s) {
        const uint32_t base = dsm_u32 + st * HSTAGE;
        uint32_t ah[4][4], al[4][4], bh2[2][4], bl2[2][4];
#pragma unroll
        for (int am = 0; am < 4; am++) {
            int row = m0 + am * 16 + rsel;
            uint32_t off = row * 128 + ((((2 * s + csel) ^ (row & 7))) << 4);
            LDSM_X4(ah[am], base + off);
            LDSM_X4(al[am], base + HTILE + off);
        }
#pragma unroll
        for (int bi = 0; bi < 2; bi++) {
            int row = n0 + bi * 16 + rsel;
            uint32_t off = row * 128 + ((((2 * s + csel) ^ (row & 7))) << 4);
            LDSM_X4(bh2[bi], base + 2 * HTILE + off);
            LDSM_X4(bl2[bi], base + 3 * HTILE + off);
        }
        // pass-major order: 16 independent accumulators between reuses
#pragma unroll
        for (int am = 0; am < 4; am++)
#pragma unroll
            for (int g = 0; g < 4; g++) {
                int bi = g >> 1, u = g & 1;
                MMA16816(acc[am][g], ah[am], bh2[bi][u], bh2[bi][u + 2]);
            }
#pragma unroll
        for (int am = 0; am < 4; am++)
#pragma unroll
            for (int g = 0; g < 4; g++) {
                int bi = g >> 1, u = g & 1;
                MMA16816(acc[am][g], ah[am], bl2[bi][u], bl2[bi][u + 2]);
            }
#pragma unroll
        for (int am = 0; am < 4; am++)
#pragma unroll
            for (int g = 0; g < 4; g++) {
                int bi = g >> 1, u = g & 1;
                MMA16816(acc[am][g], al[am], bh2[bi][u], bh2[bi][u + 2]);
            }
    };

    const int nch = K / KC;
    prefetch(0, 0);
    for (int c = 0; c < nch; c++) {
        const int st = c & 1;
        if (c + 1 < nch) { prefetch(c + 1, st ^ 1); CP_WAIT1(); }
        else             { CP_WAIT0(); }
        __syncthreads();
        mma_step(st, 0);
        mma_step(st, 1);
        mma_step(st, 2);
        mma_step(st, 3);
        __syncthreads();
    }

    // epilogue
    const int rg = lid >> 2;
    const int cg = (lid & 3) * 2;
#pragma unroll
    for (int am = 0; am < 4; am++)
#pragma unroll
        for (int g = 0; g < 4; g++) {
            int row = bm + m0 + am * 16 + rg;
            int col = bn + n0 + g * 8 + cg;
            float* p0 = C + (long)row * N + col;
            *(float2*)p0 = make_float2(alpha * acc[am][g][0], alpha * acc[am][g][1]);
            float* p1 = p0 + (long)8 * N;
            *(float2*)p1 = make_float2(alpha * acc[am][g][2], alpha * acc[am][g][3]);
        }
}

// ---------------- f32x2 helpers --------------------------------------------
__device__ __forceinline__ void ffma2(unsigned long long& d,
                                      unsigned long long a,
                                      unsigned long long b) {
    asm("fma.rn.f32x2 %0, %1, %2, %0;" : "+l"(d) : "l"(a), "l"(b));
}
__device__ __forceinline__ void unpack2f(unsigned long long v, float& lo, float& hi) {
    asm("mov.b64 {%0, %1}, %2;" : "=f"(lo), "=f"(hi) : "l"(v));
}

// ---------------- random_map = weight1 @ weight2^T -------------------------
__global__ void rmap_kernel(const float* __restrict__ w1,
                            const float* __restrict__ w2,
                            float* __restrict__ rm) {
    int idx = blockIdx.x * 256 + threadIdx.x;
    int i = idx >> 9, j = idx & 511;
    float s = 0.f;
#pragma unroll
    for (int k = 0; k < 16; k++) s += w1[i * 16 + k] * w2[j * 16 + k];
    rm[idx] = s;
}

// ---------------- batched SGEMM NN (FFMA2), 128x128x8 ----------------------
__global__ __launch_bounds__(256)
void sgemm_nn_kernel(const float* __restrict__ Ag, const float* __restrict__ Bg,
                     float* __restrict__ Cg, int M, int N, int K,
                     long strideA, long strideB, long strideC) {
    __shared__ float2 Asd[8][128];
    __shared__ float  Bs[8][128];
    const float* A = Ag + (long)blockIdx.z * strideA;
    const float* B = Bg + (long)blockIdx.z * strideB;
    float*       C = Cg + (long)blockIdx.z * strideC;
    const int bm = blockIdx.y * 128;
    const int bn = blockIdx.x * 128;
    const int tid = threadIdx.x;
    const int tx = tid & 15, ty = tid >> 4;
    const int lr  = tid >> 1;
    const int lc  = (tid & 1) * 4;
    const int bnr = tid >> 5;
    const int bnc = (tid & 31) * 4;

    unsigned long long acc[8][4];
#pragma unroll
    for (int i = 0; i < 8; i++)
#pragma unroll
        for (int j = 0; j < 4; j++) acc[i][j] = 0ull;

    for (int kt = 0; kt < K; kt += 8) {
        float4 av = *(const float4*)(A + (long)(bm + lr) * K + kt + lc);
        float4 bv = *(const float4*)(B + (long)(kt + bnr) * N + bn + bnc);
        __syncthreads();
        Asd[lc + 0][lr] = make_float2(av.x, av.x);
        Asd[lc + 1][lr] = make_float2(av.y, av.y);
        Asd[lc + 2][lr] = make_float2(av.z, av.z);
        Asd[lc + 3][lr] = make_float2(av.w, av.w);
        *(float4*)&Bs[bnr][bnc] = bv;
        __syncthreads();
#pragma unroll
        for (int k = 0; k < 8; k++) {
            const ulonglong2* ap = (const ulonglong2*)&Asd[k][ty * 8];
            ulonglong2 aA = ap[0], aB = ap[1], aC = ap[2], aD = ap[3];
            const ulonglong2* bp = (const ulonglong2*)&Bs[k][tx * 8];
            ulonglong2 bA = bp[0], bB = bp[1];
            unsigned long long aa[8] = {aA.x, aA.y, aB.x, aB.y,
                                        aC.x, aC.y, aD.x, aD.y};
            unsigned long long bb[4] = {bA.x, bA.y, bB.x, bB.y};
#pragma unroll
            for (int i = 0; i < 8; i++)
#pragma unroll
                for (int j = 0; j < 4; j++) ffma2(acc[i][j], aa[i], bb[j]);
        }
    }
#pragma unroll
    for (int i = 0; i < 8; i++) {
        float o[8];
#pragma unroll
        for (int j = 0; j < 4; j++) unpack2f(acc[i][j], o[2 * j], o[2 * j + 1]);
        float* cp = C + (long)(bm + ty * 8 + i) * N + bn + tx * 8;
        *(float4*)cp = make_float4(o[0], o[1], o[2], o[3]);
        *(float4*)(cp + 4) = make_float4(o[4], o[5], o[6], o[7]);
    }
}

// ---------------- row softmax over 512, with random_map added --------------
__global__ void softmax_kernel(float* __restrict__ S, const float* __restrict__ rmap) {
    const int c = blockIdx.x, b = blockIdx.y;
    float* row = S + ((long)b * CC + c) * CC;
    const float* rm = rmap + (long)c * CC;
    const int t = threadIdx.x;
    __shared__ float smax[4], ssum[4];
    float v[4];
#pragma unroll
    for (int j = 0; j < 4; j++) v[j] = row[t + 128 * j] + rm[t + 128 * j];
    float m = fmaxf(fmaxf(v[0], v[1]), fmaxf(v[2], v[3]));
    for (int o = 16; o; o >>= 1) m = fmaxf(m, __shfl_xor_sync(0xffffffffu, m, o));
    if ((t & 31) == 0) smax[t >> 5] = m;
    __syncthreads();
    m = fmaxf(fmaxf(smax[0], smax[1]), fmaxf(smax[2], smax[3]));
    float e[4], s = 0.f;
#pragma unroll
    for (int j = 0; j < 4; j++) { e[j] = __expf(v[j] - m); s += e[j]; }
    for (int o = 16; o; o >>= 1) s += __shfl_xor_sync(0xffffffffu, s, o);
    if ((t & 31) == 0) ssum[t >> 5] = s;
    __syncthreads();
    s = ssum[0] + ssum[1] + ssum[2] + ssum[3];
    float inv = 1.0f / s;
#pragma unroll
    for (int j = 0; j < 4; j++) row[t + 128 * j] = e[j] * inv;
}

// ---------------- launch ---------------------------------------------------
extern "C" void kernel_launch(void* const* d_in, const int* in_sizes, int n_in,
                              void* d_out, int out_size) {
    const float* x1  = (const float*)d_in[0];
    const float* x2  = (const float*)d_in[1];
    const float* g_w = (const float*)d_in[2];
    const float* w_w = (const float*)d_in[3];
    const float* w1  = (const float*)d_in[4];
    const float* w2  = (const float*)d_in[5];
    float* out = (float*)d_out;

    __nv_bfloat16 *xh, *xl, *wh, *wl, *bh, *bl;
    float *value, *attn, *rmap, *T;
    cudaGetSymbolAddress((void**)&xh, g_xh);
    cudaGetSymbolAddress((void**)&xl, g_xl);
    cudaGetSymbolAddress((void**)&wh, g_wh);
    cudaGetSymbolAddress((void**)&wl, g_wl);
    cudaGetSymbolAddress((void**)&bh, g_bh);
    cudaGetSymbolAddress((void**)&bl, g_bl);
    cudaGetSymbolAddress((void**)&value, g_value);
    cudaGetSymbolAddress((void**)&attn,  g_attn);
    cudaGetSymbolAddress((void**)&rmap,  g_rmap);
    cudaGetSymbolAddress((void**)&T,     g_T);

    cudaFuncSetAttribute(hmma_nt_kernel,
                         cudaFuncAttributeMaxDynamicSharedMemorySize, HDSMEM);

    // 1. concat + bf16 split -> Xh, Xl
    concat_split_kernel<<<BATCH * CC * 256 / 256, 256>>>(
        (const float4*)x1, (const float4*)x2, xh, xl);

    // 2. weight bf16 split -> Wh, Wl
    wsplit_kernel<<<(CC * KDIM / 4) / 256, 256>>>((const float4*)g_w, wh, wl);

    // 3. transposed bf16 im2col -> Bh, Bl
    im2colT_kernel<<<(BATCH * HW * (KDIM / 8)) / 256, 256>>>(xh, xl, bh, bl);

    // 4. value = conv3x3(x): HMMA NT  [512 x 4608] x [1024 x 4608]^T, batched
    {
        dim3 grid(HW / 128, CC / 128, BATCH);
        hmma_nt_kernel<<<grid, 256, HDSMEM>>>(wh, wl, bh, bl, value,
                                              CC, HW, KDIM,
                                              0L, (long)HW * KDIM,
                                              (long)CC * HW, 1.0f);
    }

    // 5. random_map
    rmap_kernel<<<(CC * CC) / 256, 256>>>(w1, w2, rmap);

    // 6. sim = (q @ q^T) * c^-0.5 : HMMA NT, A = B = Xh/Xl
    {
        dim3 grid(CC / 128, CC / 128, BATCH);
        hmma_nt_kernel<<<grid, 256, HDSMEM>>>(xh, xl, xh, xl, attn,
                                              CC, CC, HW,
                                              (long)CC * HW, (long)CC * HW,
                                              (long)CC * CC,
                                              1.0f / sqrtf((float)CC));
    }

    // 7. softmax(sim + rmap) in place
    {
        dim3 grid(CC, BATCH);
        softmax_kernel<<<grid, 128>>>(attn, rmap);
    }

    // 8. T = w_w @ attn
    {
        dim3 grid(CC / 128, CO / 128, BATCH);
        sgemm_nn_kernel<<<grid, 256>>>(w_w, attn, T, CO, CC, CC,
                                       0L, (long)CC * CC, (long)CO * CC);
    }

    // 9. out = T @ value
    {
        dim3 grid(HW / 128, CO / 128, BATCH);
        sgemm_nn_kernel<<<grid, 256>>>(T, value, out, CO, HW, CC,
                                       (long)CO * CC, (long)CC * HW,
                                       (long)CO * HW);
    }
}

// round 14
// speedup vs baseline: 1.7223x; 1.1469x over previous
#include <cuda_runtime.h>
#include <cuda_bf16.h>
#include <math.h>
#include <stdint.h>

// Problem constants
#define BATCH 16
#define CH    256
#define CC    512
#define HW    1024
#define KDIM  (CC * 9)     // 4608
#define CO    256

// ---------------- scratch (device globals: allocation-free) ----------------
__device__ __nv_bfloat16 g_xh[BATCH * CC * HW];
__device__ __nv_bfloat16 g_xl[BATCH * CC * HW];
__device__ __nv_bfloat16 g_wh[CC * KDIM];
__device__ __nv_bfloat16 g_wl[CC * KDIM];
__device__ __nv_bfloat16 g_bh[(size_t)BATCH * HW * KDIM];   // im2col^T hi
__device__ __nv_bfloat16 g_bl[(size_t)BATCH * HW * KDIM];   // im2col^T lo
__device__ float g_value[BATCH * CC * HW];
__device__ float g_attn [BATCH * CC * CC];
__device__ float g_rmap [CC * CC];
__device__ float g_T    [BATCH * CO * CC];
__device__ __nv_bfloat16 g_ath[BATCH * CC * CC];            // attn^T hi
__device__ __nv_bfloat16 g_atl[BATCH * CC * CC];            // attn^T lo
__device__ __nv_bfloat16 g_vth[BATCH * HW * CC];            // value^T hi
__device__ __nv_bfloat16 g_vtl[BATCH * HW * CC];            // value^T lo
__device__ __nv_bfloat16 g_th [BATCH * CO * CC];            // T hi
__device__ __nv_bfloat16 g_tl [BATCH * CO * CC];            // T lo
__device__ __nv_bfloat16 g_wwh[CO * CC];
__device__ __nv_bfloat16 g_wwl[CO * CC];

__device__ __forceinline__ uint32_t smem_to_u32(const void* p) {
    uint32_t a;
    asm("{ .reg .u64 t; cvta.to.shared.u64 t, %1; cvt.u32.u64 %0, t; }"
        : "=r"(a) : "l"(p));
    return a;
}

// ---------------- warp-mma building blocks ---------------------------------
#define LDSM_X4(R, ADDR) \
    asm volatile("ldmatrix.sync.aligned.m8n8.x4.shared.b16 {%0,%1,%2,%3}, [%4];" \
        : "=r"((R)[0]), "=r"((R)[1]), "=r"((R)[2]), "=r"((R)[3]) : "r"(ADDR))

#define MMA16816(D, A, B0, B1) \
    asm volatile("mma.sync.aligned.m16n8k16.row.col.f32.bf16.bf16.f32 " \
        "{%0,%1,%2,%3}, {%4,%5,%6,%7}, {%8,%9}, {%0,%1,%2,%3};" \
        : "+f"((D)[0]), "+f"((D)[1]), "+f"((D)[2]), "+f"((D)[3]) \
        : "r"((A)[0]), "r"((A)[1]), "r"((A)[2]), "r"((A)[3]), "r"(B0), "r"(B1))

__device__ __forceinline__ void cp16(uint32_t s, const void* g) {
    asm volatile("cp.async.cg.shared.global [%0], [%1], 16;" :: "r"(s), "l"(g));
}
#define CP_COMMIT() asm volatile("cp.async.commit_group;" ::: "memory")
#define CP_WAIT2()  asm volatile("cp.async.wait_group 2;" ::: "memory")
#define CP_WAIT1()  asm volatile("cp.async.wait_group 1;" ::: "memory")
#define CP_WAIT0()  asm volatile("cp.async.wait_group 0;" ::: "memory")

__device__ __forceinline__ void split2(float x, float y, uint32_t& hi, uint32_t& lo) {
    __nv_bfloat16 hx = __float2bfloat16(x), hy = __float2bfloat16(y);
    __nv_bfloat16 lx = __float2bfloat16(x - __bfloat162float(hx));
    __nv_bfloat16 ly = __float2bfloat16(y - __bfloat162float(hy));
    hi = ((uint32_t)__bfloat16_as_ushort(hy) << 16) | __bfloat16_as_ushort(hx);
    lo = ((uint32_t)__bfloat16_as_ushort(ly) << 16) | __bfloat16_as_ushort(lx);
}

// ============ concat + bf16 split: x1,x2 -> Xh, Xl [b][c][sp] ==============
__global__ void concat_split_kernel(const float4* __restrict__ x1,
                                    const float4* __restrict__ x2,
                                    __nv_bfloat16* __restrict__ xh,
                                    __nv_bfloat16* __restrict__ xl) {
    int idx = blockIdx.x * 256 + threadIdx.x;
    int p = idx & 255;
    int c = (idx >> 8) & 511;
    int b = idx >> 17;
    float4 v = (c < CH) ? x1[((b << 8) + c) * 256 + p]
                        : x2[((b << 8) + (c - CH)) * 256 + p];
    uint32_t h0, l0, h1, l1;
    split2(v.x, v.y, h0, l0);
    split2(v.z, v.w, h1, l1);
    *(uint2*)(xh + (size_t)idx * 4) = make_uint2(h0, h1);
    *(uint2*)(xl + (size_t)idx * 4) = make_uint2(l0, l1);
}

// ============ flat bf16 split (weights / T): size = 4*gridDim*256 elems ====
__global__ void fsplit_kernel(const float4* __restrict__ w,
                              __nv_bfloat16* __restrict__ wh,
                              __nv_bfloat16* __restrict__ wl) {
    int idx = blockIdx.x * 256 + threadIdx.x;
    float4 v = w[idx];
    uint32_t h0, l0, h1, l1;
    split2(v.x, v.y, h0, l0);
    split2(v.z, v.w, h1, l1);
    *(uint2*)(wh + (size_t)idx * 4) = make_uint2(h0, h1);
    *(uint2*)(wl + (size_t)idx * 4) = make_uint2(l0, l1);
}

// ============ transpose + split: in fp32 [R][Cc] -> out bf16 [Cc][R] =======
__global__ void tsplit_kernel(const float* __restrict__ in,
                              __nv_bfloat16* __restrict__ oh,
                              __nv_bfloat16* __restrict__ ol,
                              int R, int Ccols, long sIn, long sOut) {
    __shared__ float t[32][33];
    const float* ip = in + (long)blockIdx.z * sIn;
    __nv_bfloat16* oph = oh + (long)blockIdx.z * sOut;
    __nv_bfloat16* opl = ol + (long)blockIdx.z * sOut;
    int tx = threadIdx.x, ty = threadIdx.y;     // 32 x 8
    int r0 = blockIdx.y * 32, c0 = blockIdx.x * 32;
#pragma unroll
    for (int j = 0; j < 4; j++)
        t[ty + 8 * j][tx] = ip[(long)(r0 + ty + 8 * j) * Ccols + c0 + tx];
    __syncthreads();
#pragma unroll
    for (int j = 0; j < 4; j++) {
        float v = t[tx][ty + 8 * j];
        __nv_bfloat16 h = __float2bfloat16(v);
        __nv_bfloat16 l = __float2bfloat16(v - __bfloat162float(h));
        long o = (long)(c0 + ty + 8 * j) * R + r0 + tx;
        oph[o] = h; opl[o] = l;
    }
}

// ============ transposed im2col in bf16: Bh/Bl[b][n][k] ====================
__global__ void im2colT_kernel(const __nv_bfloat16* __restrict__ xh,
                               const __nv_bfloat16* __restrict__ xl,
                               __nv_bfloat16* __restrict__ bh,
                               __nv_bfloat16* __restrict__ bl) {
    int idx = blockIdx.x * 256 + threadIdx.x;
    int g = idx % 576;
    int n = (idx / 576) & 1023;
    int b = idx / (576 * 1024);
    int k0 = g * 8;
    int ci = k0 / 9;
    int r9 = k0 - ci * 9;
    int y0 = n >> 5, x0 = n & 31;
    const unsigned short* Xh = (const unsigned short*)(xh + ((long)b << 19));
    const unsigned short* Xl = (const unsigned short*)(xl + ((long)b << 19));
    unsigned short hv[8], lv[8];
#pragma unroll
    for (int kk = 0; kk < 8; kk++) {
        int ky = (r9 >= 6) ? 2 : ((r9 >= 3) ? 1 : 0);
        int kx = r9 - ky * 3;
        int y = y0 + ky - 1, x = x0 + kx - 1;
        unsigned short h = 0, l = 0;
        if ((unsigned)y < 32u && (unsigned)x < 32u) {
            int o = (ci << 10) + (y << 5) + x;
            h = Xh[o]; l = Xl[o];
        }
        hv[kk] = h; lv[kk] = l;
        if (++r9 == 9) { r9 = 0; ci++; }
    }
    uint4 ph, pl;
    ph.x = hv[0] | ((uint32_t)hv[1] << 16); ph.y = hv[2] | ((uint32_t)hv[3] << 16);
    ph.z = hv[4] | ((uint32_t)hv[5] << 16); ph.w = hv[6] | ((uint32_t)hv[7] << 16);
    pl.x = lv[0] | ((uint32_t)lv[1] << 16); pl.y = lv[2] | ((uint32_t)lv[3] << 16);
    pl.z = lv[4] | ((uint32_t)lv[5] << 16); pl.w = lv[6] | ((uint32_t)lv[7] << 16);
    size_t base = (size_t)idx * 8;
    *(uint4*)((unsigned short*)bh + base) = ph;
    *(uint4*)((unsigned short*)bl + base) = pl;
}

// ============ generic NT HMMA GEMM, bf16 3-pass split ======================
// KC=32 (64B rows), 3-stage cp.async ring, 2 CTAs/SM.
#define KC       32
#define HTILE    8192                  // 128 rows x 64 bytes
#define HSTAGE   (4 * HTILE)           // Ah, Al, Bh, Bl = 32 KB
#define HSTAGES  3
#define HDSMEM   (1024 + HSTAGES * HSTAGE)

__global__ __launch_bounds__(256, 2)
void hmma_nt_kernel(const __nv_bfloat16* __restrict__ Ahg,
                    const __nv_bfloat16* __restrict__ Alg,
                    const __nv_bfloat16* __restrict__ Bhg,
                    const __nv_bfloat16* __restrict__ Blg,
                    float* __restrict__ Cg,
                    int M, int N, int K,
                    long sA, long sB, long sC, float alpha) {
    extern __shared__ char dsm_raw[];
    char* dsm = (char*)(((uintptr_t)dsm_raw + 1023) & ~(uintptr_t)1023);
    const uint32_t dsm_u32 = smem_to_u32(dsm);

    const int tid = threadIdx.x;
    const int wid = tid >> 5;
    const int lid = tid & 31;
    const int m0 = (wid >> 2) * 64;
    const int n0 = (wid & 3) * 32;
    const int bm = blockIdx.y * 128;
    const int bn = blockIdx.x * 128;
    const int b  = blockIdx.z;

    const __nv_bfloat16* Ah = Ahg + (long)b * sA;
    const __nv_bfloat16* Al = Alg + (long)b * sA;
    const __nv_bfloat16* Bh = Bhg + (long)b * sB;
    const __nv_bfloat16* Bl = Blg + (long)b * sB;
    float* C = Cg + (long)b * sC;

    const int frow = tid >> 1;       // 0..127
    const int fhalf = tid & 1;       // k offset 0 / 16

    float acc[4][4][4];
#pragma unroll
    for (int i = 0; i < 4; i++)
#pragma unroll
        for (int j = 0; j < 4; j++)
#pragma unroll
            for (int q = 0; q < 4; q++) acc[i][j][q] = 0.f;

    // swizzle for 64B rows: chunk ^ ((row>>1)&3)
    auto prefetch = [&](int c, int st) {
        const long kb = (long)c * KC + fhalf * 16;
        const uint32_t so = dsm_u32 + st * HSTAGE;
        const __nv_bfloat16* pAh = Ah + (long)(bm + frow) * K + kb;
        const __nv_bfloat16* pAl = Al + (long)(bm + frow) * K + kb;
        const __nv_bfloat16* pBh = Bh + (long)(bn + frow) * K + kb;
        const __nv_bfloat16* pBl = Bl + (long)(bn + frow) * K + kb;
#pragma unroll
        for (int j = 0; j < 2; j++) {
            int chunk = fhalf * 2 + j;
            uint32_t off = frow * 64 + (((chunk ^ ((frow >> 1) & 3))) << 4);
            cp16(so + off,              pAh + j * 8);
            cp16(so + HTILE + off,      pAl + j * 8);
            cp16(so + 2 * HTILE + off,  pBh + j * 8);
            cp16(so + 3 * HTILE + off,  pBl + j * 8);
        }
        CP_COMMIT();
    };

    const int rsel = lid & 15, csel = lid >> 4;
    auto mma_step = [&](int st, int s) {
        const uint32_t base = dsm_u32 + st * HSTAGE;
        uint32_t ah[4][4], al[4][4], bh2[2][4], bl2[2][4];
#pragma unroll
        for (int am = 0; am < 4; am++) {
            int row = m0 + am * 16 + rsel;
            uint32_t off = row * 64 + ((((2 * s + csel) ^ ((row >> 1) & 3))) << 4);
            LDSM_X4(ah[am], base + off);
            LDSM_X4(al[am], base + HTILE + off);
        }
#pragma unroll
        for (int bi = 0; bi < 2; bi++) {
            int row = n0 + bi * 16 + rsel;
            uint32_t off = row * 64 + ((((2 * s + csel) ^ ((row >> 1) & 3))) << 4);
            LDSM_X4(bh2[bi], base + 2 * HTILE + off);
            LDSM_X4(bl2[bi], base + 3 * HTILE + off);
        }
#pragma unroll
        for (int am = 0; am < 4; am++)
#pragma unroll
            for (int g = 0; g < 4; g++) {
                int bi = g >> 1, u = g & 1;
                MMA16816(acc[am][g], ah[am], bh2[bi][u], bh2[bi][u + 2]);
            }
#pragma unroll
        for (int am = 0; am < 4; am++)
#pragma unroll
            for (int g = 0; g < 4; g++) {
                int bi = g >> 1, u = g & 1;
                MMA16816(acc[am][g], ah[am], bl2[bi][u], bl2[bi][u + 2]);
            }
#pragma unroll
        for (int am = 0; am < 4; am++)
#pragma unroll
            for (int g = 0; g < 4; g++) {
                int bi = g >> 1, u = g & 1;
                MMA16816(acc[am][g], al[am], bh2[bi][u], bh2[bi][u + 2]);
            }
    };

    const int nch = K / KC;
    prefetch(0, 0);
    if (nch > 1) prefetch(1, 1);
    int st = 0;
    for (int c = 0; c < nch; c++) {
        if (c + 2 < nch) { prefetch(c + 2, (st + 2) % HSTAGES); CP_WAIT2(); }
        else if (c + 1 < nch) { CP_WAIT1(); }
        else { CP_WAIT0(); }
        __syncthreads();
        mma_step(st, 0);
        mma_step(st, 1);
        __syncthreads();
        st = (st + 1 == HSTAGES) ? 0 : st + 1;
    }

    // epilogue
    const int rg = lid >> 2;
    const int cg = (lid & 3) * 2;
#pragma unroll
    for (int am = 0; am < 4; am++)
#pragma unroll
        for (int g = 0; g < 4; g++) {
            int row = bm + m0 + am * 16 + rg;
            int col = bn + n0 + g * 8 + cg;
            float* p0 = C + (long)row * N + col;
            *(float2*)p0 = make_float2(alpha * acc[am][g][0], alpha * acc[am][g][1]);
            float* p1 = p0 + (long)8 * N;
            *(float2*)p1 = make_float2(alpha * acc[am][g][2], alpha * acc[am][g][3]);
        }
}

// ---------------- random_map = weight1 @ weight2^T -------------------------
__global__ void rmap_kernel(const float* __restrict__ w1,
                            const float* __restrict__ w2,
                            float* __restrict__ rm) {
    int idx = blockIdx.x * 256 + threadIdx.x;
    int i = idx >> 9, j = idx & 511;
    float s = 0.f;
#pragma unroll
    for (int k = 0; k < 16; k++) s += w1[i * 16 + k] * w2[j * 16 + k];
    rm[idx] = s;
}

// ---------------- row softmax over 512, with random_map added --------------
__global__ void softmax_kernel(float* __restrict__ S, const float* __restrict__ rmap) {
    const int c = blockIdx.x, b = blockIdx.y;
    float* row = S + ((long)b * CC + c) * CC;
    const float* rm = rmap + (long)c * CC;
    const int t = threadIdx.x;
    __shared__ float smax[4], ssum[4];
    float v[4];
#pragma unroll
    for (int j = 0; j < 4; j++) v[j] = row[t + 128 * j] + rm[t + 128 * j];
    float m = fmaxf(fmaxf(v[0], v[1]), fmaxf(v[2], v[3]));
    for (int o = 16; o; o >>= 1) m = fmaxf(m, __shfl_xor_sync(0xffffffffu, m, o));
    if ((t & 31) == 0) smax[t >> 5] = m;
    __syncthreads();
    m = fmaxf(fmaxf(smax[0], smax[1]), fmaxf(smax[2], smax[3]));
    float e[4], s = 0.f;
#pragma unroll
    for (int j = 0; j < 4; j++) { e[j] = __expf(v[j] - m); s += e[j]; }
    for (int o = 16; o; o >>= 1) s += __shfl_xor_sync(0xffffffffu, s, o);
    if ((t & 31) == 0) ssum[t >> 5] = s;
    __syncthreads();
    s = ssum[0] + ssum[1] + ssum[2] + ssum[3];
    float inv = 1.0f / s;
#pragma unroll
    for (int j = 0; j < 4; j++) row[t + 128 * j] = e[j] * inv;
}

// ---------------- launch ---------------------------------------------------
extern "C" void kernel_launch(void* const* d_in, const int* in_sizes, int n_in,
                              void* d_out, int out_size) {
    const float* x1  = (const float*)d_in[0];
    const float* x2  = (const float*)d_in[1];
    const float* g_w = (const float*)d_in[2];
    const float* w_w = (const float*)d_in[3];
    const float* w1  = (const float*)d_in[4];
    const float* w2  = (const float*)d_in[5];
    float* out = (float*)d_out;

    __nv_bfloat16 *xh, *xl, *wh, *wl, *bh, *bl;
    __nv_bfloat16 *ath, *atl, *vth, *vtl, *th, *tl, *wwh, *wwl;
    float *value, *attn, *rmap, *T;
    cudaGetSymbolAddress((void**)&xh, g_xh);
    cudaGetSymbolAddress((void**)&xl, g_xl);
    cudaGetSymbolAddress((void**)&wh, g_wh);
    cudaGetSymbolAddress((void**)&wl, g_wl);
    cudaGetSymbolAddress((void**)&bh, g_bh);
    cudaGetSymbolAddress((void**)&bl, g_bl);
    cudaGetSymbolAddress((void**)&ath, g_ath);
    cudaGetSymbolAddress((void**)&atl, g_atl);
    cudaGetSymbolAddress((void**)&vth, g_vth);
    cudaGetSymbolAddress((void**)&vtl, g_vtl);
    cudaGetSymbolAddress((void**)&th, g_th);
    cudaGetSymbolAddress((void**)&tl, g_tl);
    cudaGetSymbolAddress((void**)&wwh, g_wwh);
    cudaGetSymbolAddress((void**)&wwl, g_wwl);
    cudaGetSymbolAddress((void**)&value, g_value);
    cudaGetSymbolAddress((void**)&attn,  g_attn);
    cudaGetSymbolAddress((void**)&rmap,  g_rmap);
    cudaGetSymbolAddress((void**)&T,     g_T);

    cudaFuncSetAttribute(hmma_nt_kernel,
                         cudaFuncAttributeMaxDynamicSharedMemorySize, HDSMEM);

    // 1. concat + bf16 split -> Xh, Xl
    concat_split_kernel<<<BATCH * CC * 256 / 256, 256>>>(
        (const float4*)x1, (const float4*)x2, xh, xl);

    // 2. weight splits
    fsplit_kernel<<<(CC * KDIM / 4) / 256, 256>>>((const float4*)g_w, wh, wl);
    fsplit_kernel<<<(CO * CC / 4) / 256, 256>>>((const float4*)w_w, wwh, wwl);

    // 3. transposed bf16 im2col -> Bh, Bl
    im2colT_kernel<<<(BATCH * HW * (KDIM / 8)) / 256, 256>>>(xh, xl, bh, bl);

    // 4. value = conv3x3(x): HMMA NT [512 x 4608] x [1024 x 4608]^T
    {
        dim3 grid(HW / 128, CC / 128, BATCH);
        hmma_nt_kernel<<<grid, 256, HDSMEM>>>(wh, wl, bh, bl, value,
                                              CC, HW, KDIM,
                                              0L, (long)HW * KDIM,
                                              (long)CC * HW, 1.0f);
    }

    // 5. random_map
    rmap_kernel<<<(CC * CC) / 256, 256>>>(w1, w2, rmap);

    // 6. sim = (q @ q^T) * c^-0.5
    {
        dim3 grid(CC / 128, CC / 128, BATCH);
        hmma_nt_kernel<<<grid, 256, HDSMEM>>>(xh, xl, xh, xl, attn,
                                              CC, CC, HW,
                                              (long)CC * HW, (long)CC * HW,
                                              (long)CC * CC,
                                              1.0f / sqrtf((float)CC));
    }

    // 7. softmax(sim + rmap) in place
    {
        dim3 grid(CC, BATCH);
        softmax_kernel<<<grid, 128>>>(attn, rmap);
    }

    // 8a. attn^T split (for NT GEMM B operand)
    {
        dim3 grid(CC / 32, CC / 32, BATCH);
        tsplit_kernel<<<grid, dim3(32, 8)>>>(attn, ath, atl, CC, CC,
                                             (long)CC * CC, (long)CC * CC);
    }
    // 8b. value^T split
    {
        dim3 grid(HW / 32, CC / 32, BATCH);
        tsplit_kernel<<<grid, dim3(32, 8)>>>(value, vth, vtl, CC, HW,
                                             (long)CC * HW, (long)CC * HW);
    }

    // 8c. T = w_w @ attn : HMMA NT, A=ww [256x512], B=attn^T [512x512]
    {
        dim3 grid(CC / 128, CO / 128, BATCH);
        hmma_nt_kernel<<<grid, 256, HDSMEM>>>(wwh, wwl, ath, atl, T,
                                              CO, CC, CC,
                                              0L, (long)CC * CC,
                                              (long)CO * CC, 1.0f);
    }

    // 8d. T split
    fsplit_kernel<<<(BATCH * CO * CC / 4) / 256, 256>>>((const float4*)T, th, tl);

    // 9. out = T @ value : HMMA NT, A=T [256x512], B=value^T [1024x512]
    {
        dim3 grid(HW / 128, CO / 128, BATCH);
        hmma_nt_kernel<<<grid, 256, HDSMEM>>>(th, tl, vth, vtl, out,
                                              CO, HW, CC,
                                              (long)CO * CC, (long)HW * CC,
                                              (long)CO * HW, 1.0f);
    }
}

// round 15
// speedup vs baseline: 2.3257x; 1.3503x over previous
#include <cuda_runtime.h>
#include <cuda_bf16.h>
#include <math.h>
#include <stdint.h>

// Problem constants
#define BATCH 16
#define CH    256
#define CC    512
#define HW    1024
#define KDIM  (CC * 9)     // 4608
#define CO    256

// ---------------- scratch (device globals: allocation-free) ----------------
__device__ __nv_bfloat16 g_xh [BATCH * CC * HW];    // X  [b][c][n] hi (sim operand)
__device__ __nv_bfloat16 g_xl [BATCH * CC * HW];
__device__ __nv_bfloat16 g_xth[BATCH * HW * CC];    // X^T [b][n][c] hi (conv B operand)
__device__ __nv_bfloat16 g_xtl[BATCH * HW * CC];
__device__ __nv_bfloat16 g_wh [CC * KDIM];          // W permuted k=(t,ci), hi
__device__ __nv_bfloat16 g_wl [CC * KDIM];
__device__ float g_value[BATCH * CC * HW];
__device__ float g_attn [BATCH * CC * CC];
__device__ float g_rmap [CC * CC];
__device__ float g_T    [BATCH * CO * CC];
__device__ __nv_bfloat16 g_ath[BATCH * CC * CC];    // attn^T hi/lo
__device__ __nv_bfloat16 g_atl[BATCH * CC * CC];
__device__ __nv_bfloat16 g_vth[BATCH * HW * CC];    // value^T hi/lo
__device__ __nv_bfloat16 g_vtl[BATCH * HW * CC];
__device__ __nv_bfloat16 g_th [BATCH * CO * CC];    // T hi/lo
__device__ __nv_bfloat16 g_tl [BATCH * CO * CC];
__device__ __nv_bfloat16 g_wwh[CO * CC];
__device__ __nv_bfloat16 g_wwl[CO * CC];

__device__ __forceinline__ uint32_t smem_to_u32(const void* p) {
    uint32_t a;
    asm("{ .reg .u64 t; cvta.to.shared.u64 t, %1; cvt.u32.u64 %0, t; }"
        : "=r"(a) : "l"(p));
    return a;
}

// ---------------- warp-mma building blocks ---------------------------------
#define LDSM_X4(R, ADDR) \
    asm volatile("ldmatrix.sync.aligned.m8n8.x4.shared.b16 {%0,%1,%2,%3}, [%4];" \
        : "=r"((R)[0]), "=r"((R)[1]), "=r"((R)[2]), "=r"((R)[3]) : "r"(ADDR))

#define MMA16816(D, A, B0, B1) \
    asm volatile("mma.sync.aligned.m16n8k16.row.col.f32.bf16.bf16.f32 " \
        "{%0,%1,%2,%3}, {%4,%5,%6,%7}, {%8,%9}, {%0,%1,%2,%3};" \
        : "+f"((D)[0]), "+f"((D)[1]), "+f"((D)[2]), "+f"((D)[3]) \
        : "r"((A)[0]), "r"((A)[1]), "r"((A)[2]), "r"((A)[3]), "r"(B0), "r"(B1))

__device__ __forceinline__ void cp16(uint32_t s, const void* g) {
    asm volatile("cp.async.cg.shared.global [%0], [%1], 16;" :: "r"(s), "l"(g));
}
// zero-fill variant: copies `sz` bytes (0 or 16), zero-fills the rest
__device__ __forceinline__ void cp16z(uint32_t s, const void* g, uint32_t sz) {
    asm volatile("cp.async.cg.shared.global [%0], [%1], 16, %2;"
                 :: "r"(s), "l"(g), "r"(sz));
}
#define CP_COMMIT() asm volatile("cp.async.commit_group;" ::: "memory")
#define CP_WAIT2()  asm volatile("cp.async.wait_group 2;" ::: "memory")
#define CP_WAIT1()  asm volatile("cp.async.wait_group 1;" ::: "memory")
#define CP_WAIT0()  asm volatile("cp.async.wait_group 0;" ::: "memory")

__device__ __forceinline__ void split2(float x, float y, uint32_t& hi, uint32_t& lo) {
    __nv_bfloat16 hx = __float2bfloat16(x), hy = __float2bfloat16(y);
    __nv_bfloat16 lx = __float2bfloat16(x - __bfloat162float(hx));
    __nv_bfloat16 ly = __float2bfloat16(y - __bfloat162float(hy));
    hi = ((uint32_t)__bfloat16_as_ushort(hy) << 16) | __bfloat16_as_ushort(hx);
    lo = ((uint32_t)__bfloat16_as_ushort(ly) << 16) | __bfloat16_as_ushort(lx);
}

// ============ concat + bf16 split: x1,x2 -> Xh, Xl [b][c][sp] ==============
__global__ void concat_split_kernel(const float4* __restrict__ x1,
                                    const float4* __restrict__ x2,
                                    __nv_bfloat16* __restrict__ xh,
                                    __nv_bfloat16* __restrict__ xl) {
    int idx = blockIdx.x * 256 + threadIdx.x;
    int p = idx & 255;
    int c = (idx >> 8) & 511;
    int b = idx >> 17;
    float4 v = (c < CH) ? x1[((b << 8) + c) * 256 + p]
                        : x2[((b << 8) + (c - CH)) * 256 + p];
    uint32_t h0, l0, h1, l1;
    split2(v.x, v.y, h0, l0);
    split2(v.z, v.w, h1, l1);
    *(uint2*)(xh + (size_t)idx * 4) = make_uint2(h0, h1);
    *(uint2*)(xl + (size_t)idx * 4) = make_uint2(l0, l1);
}

// ============ concat + transpose + split: -> X^T [b][n][c] bf16 ============
__global__ void xt_split_kernel(const float* __restrict__ x1,
                                const float* __restrict__ x2,
                                __nv_bfloat16* __restrict__ oh,
                                __nv_bfloat16* __restrict__ ol) {
    __shared__ float t[32][33];
    int b = blockIdx.z;
    int c0 = blockIdx.y * 32, n0 = blockIdx.x * 32;
    int tx = threadIdx.x, ty = threadIdx.y;     // 32 x 8
    const float* src = (c0 < CH) ? (x1 + ((long)b * CH + c0) * HW)
                                 : (x2 + ((long)b * CH + (c0 - CH)) * HW);
#pragma unroll
    for (int j = 0; j < 4; j++)
        t[ty + 8 * j][tx] = src[(long)(ty + 8 * j) * HW + n0 + tx];
    __syncthreads();
    __nv_bfloat16* oph = oh + (long)b * HW * CC;
    __nv_bfloat16* opl = ol + (long)b * HW * CC;
#pragma unroll
    for (int j = 0; j < 4; j++) {
        float v = t[tx][ty + 8 * j];
        __nv_bfloat16 h = __float2bfloat16(v);
        __nv_bfloat16 l = __float2bfloat16(v - __bfloat162float(h));
        long o = (long)(n0 + ty + 8 * j) * CC + c0 + tx;
        oph[o] = h; opl[o] = l;
    }
}

// ============ weight permute+split: Wp[m][t*512+ci] = W[m][ci*9+t] =========
__global__ void wperm_split_kernel(const float* __restrict__ w,
                                   __nv_bfloat16* __restrict__ wh,
                                   __nv_bfloat16* __restrict__ wl) {
    int idx = blockIdx.x * 256 + threadIdx.x;   // 512*4608
    int k = idx % KDIM;
    int m = idx / KDIM;
    int t = k >> 9, ci = k & 511;
    float v = w[(long)m * KDIM + ci * 9 + t];
    __nv_bfloat16 h = __float2bfloat16(v);
    __nv_bfloat16 l = __float2bfloat16(v - __bfloat162float(h));
    wh[idx] = h; wl[idx] = l;
}

// ============ flat bf16 split ==============================================
__global__ void fsplit_kernel(const float4* __restrict__ w,
                              __nv_bfloat16* __restrict__ wh,
                              __nv_bfloat16* __restrict__ wl) {
    int idx = blockIdx.x * 256 + threadIdx.x;
    float4 v = w[idx];
    uint32_t h0, l0, h1, l1;
    split2(v.x, v.y, h0, l0);
    split2(v.z, v.w, h1, l1);
    *(uint2*)(wh + (size_t)idx * 4) = make_uint2(h0, h1);
    *(uint2*)(wl + (size_t)idx * 4) = make_uint2(l0, l1);
}

// ============ transpose + split: fp32 [R][Cc] -> bf16 [Cc][R] ==============
__global__ void tsplit_kernel(const float* __restrict__ in,
                              __nv_bfloat16* __restrict__ oh,
                              __nv_bfloat16* __restrict__ ol,
                              int R, int Ccols, long sIn, long sOut) {
    __shared__ float t[32][33];
    const float* ip = in + (long)blockIdx.z * sIn;
    __nv_bfloat16* oph = oh + (long)blockIdx.z * sOut;
    __nv_bfloat16* opl = ol + (long)blockIdx.z * sOut;
    int tx = threadIdx.x, ty = threadIdx.y;     // 32 x 8
    int r0 = blockIdx.y * 32, c0 = blockIdx.x * 32;
#pragma unroll
    for (int j = 0; j < 4; j++)
        t[ty + 8 * j][tx] = ip[(long)(r0 + ty + 8 * j) * Ccols + c0 + tx];
    __syncthreads();
#pragma unroll
    for (int j = 0; j < 4; j++) {
        float v = t[tx][ty + 8 * j];
        __nv_bfloat16 h = __float2bfloat16(v);
        __nv_bfloat16 l = __float2bfloat16(v - __bfloat162float(h));
        long o = (long)(c0 + ty + 8 * j) * R + r0 + tx;
        oph[o] = h; opl[o] = l;
    }
}

// ============ shared GEMM config ===========================================
#define KC       32
#define HTILE    8192                  // 128 rows x 64 bytes
#define HSTAGE   (4 * HTILE)           // Ah, Al, Bh, Bl = 32 KB
#define HSTAGES  3
#define HDSMEM   (1024 + HSTAGES * HSTAGE)

// mma core shared by both GEMM kernels (acc += (Ah+Al)*(Bh+Bl), lo*lo dropped)
#define MMA_STEP_BODY(base)                                                    \
    uint32_t ah[4][4], al[4][4], bh2[2][4], bl2[2][4];                         \
    _Pragma("unroll")                                                          \
    for (int am = 0; am < 4; am++) {                                           \
        int row = m0 + am * 16 + rsel;                                         \
        uint32_t off = row * 64 + ((((2 * s + csel) ^ ((row >> 1) & 3))) << 4);\
        LDSM_X4(ah[am], (base) + off);                                         \
        LDSM_X4(al[am], (base) + HTILE + off);                                 \
    }                                                                          \
    _Pragma("unroll")                                                          \
    for (int bi = 0; bi < 2; bi++) {                                           \
        int row = n0 + bi * 16 + rsel;                                         \
        uint32_t off = row * 64 + ((((2 * s + csel) ^ ((row >> 1) & 3))) << 4);\
        LDSM_X4(bh2[bi], (base) + 2 * HTILE + off);                            \
        LDSM_X4(bl2[bi], (base) + 3 * HTILE + off);                            \
    }                                                                          \
    _Pragma("unroll")                                                          \
    for (int am = 0; am < 4; am++)                                             \
        _Pragma("unroll")                                                      \
        for (int g = 0; g < 4; g++) {                                          \
            int bi = g >> 1, u = g & 1;                                        \
            MMA16816(acc[am][g], ah[am], bh2[bi][u], bh2[bi][u + 2]);          \
        }                                                                      \
    _Pragma("unroll")                                                          \
    for (int am = 0; am < 4; am++)                                             \
        _Pragma("unroll")                                                      \
        for (int g = 0; g < 4; g++) {                                          \
            int bi = g >> 1, u = g & 1;                                        \
            MMA16816(acc[am][g], ah[am], bl2[bi][u], bl2[bi][u + 2]);          \
        }                                                                      \
    _Pragma("unroll")                                                          \
    for (int am = 0; am < 4; am++)                                             \
        _Pragma("unroll")                                                      \
        for (int g = 0; g < 4; g++) {                                          \
            int bi = g >> 1, u = g & 1;                                        \
            MMA16816(acc[am][g], al[am], bh2[bi][u], bh2[bi][u + 2]);          \
        }

// ============ conv GEMM: B = shifted X^T, no materialized im2col ===========
// value[b][m][n] = sum_{t,ci} Wp[m][t*512+ci] * XT[b][shift_t(n)][ci]
__global__ __launch_bounds__(256, 2)
void conv_hmma_kernel(const __nv_bfloat16* __restrict__ Wh,
                      const __nv_bfloat16* __restrict__ Wl,
                      const __nv_bfloat16* __restrict__ XTh,
                      const __nv_bfloat16* __restrict__ XTl,
                      float* __restrict__ Cg) {
    extern __shared__ char dsm_raw[];
    char* dsm = (char*)(((uintptr_t)dsm_raw + 1023) & ~(uintptr_t)1023);
    const uint32_t dsm_u32 = smem_to_u32(dsm);

    const int tid = threadIdx.x;
    const int wid = tid >> 5;
    const int lid = tid & 31;
    const int m0 = (wid >> 2) * 64;
    const int n0 = (wid & 3) * 32;
    const int bm = blockIdx.y * 128;
    const int bn = blockIdx.x * 128;
    const int b  = blockIdx.z;

    const __nv_bfloat16* Bh = XTh + (long)b * HW * CC;
    const __nv_bfloat16* Bl = XTl + (long)b * HW * CC;
    float* C = Cg + (long)b * CC * HW;

    const int frow = tid >> 1;       // 0..127
    const int fhalf = tid & 1;       // k offset 0 / 16
    // spatial coords of this thread's B row
    const int sp = bn + frow;
    const int sy = sp >> 5, sx = sp & 31;

    float acc[4][4][4];
#pragma unroll
    for (int i = 0; i < 4; i++)
#pragma unroll
        for (int j = 0; j < 4; j++)
#pragma unroll
            for (int q = 0; q < 4; q++) acc[i][j][q] = 0.f;

    auto prefetch = [&](int c, int st) {
        const uint32_t so = dsm_u32 + st * HSTAGE;
        // A: permuted weights, contiguous k
        const long kb = (long)c * KC + fhalf * 16;
        const __nv_bfloat16* pAh = Wh + (long)(bm + frow) * KDIM + kb;
        const __nv_bfloat16* pAl = Wl + (long)(bm + frow) * KDIM + kb;
        // B: shifted XT row for tap t = c>>4
        const int t = c >> 4;
        const int dy = (t >= 6) ? 1 : ((t >= 3) ? 0 : -1);
        const int dx = t - (dy + 1) * 3 - 1;
        const int y = sy + dy, x = sx + dx;
        const bool ok = ((unsigned)y < 32u) & ((unsigned)x < 32u);
        const uint32_t sz = ok ? 16u : 0u;
        const long bsrc = ok ? ((long)((y << 5) + x) * CC + (c & 15) * 32 + fhalf * 16)
                             : 0L;
        const __nv_bfloat16* pBh = Bh + bsrc;
        const __nv_bfloat16* pBl = Bl + bsrc;
#pragma unroll
        for (int j = 0; j < 2; j++) {
            int chunk = fhalf * 2 + j;
            uint32_t off = frow * 64 + (((chunk ^ ((frow >> 1) & 3))) << 4);
            cp16(so + off,                  pAh + j * 8);
            cp16(so + HTILE + off,          pAl + j * 8);
            cp16z(so + 2 * HTILE + off,     pBh + j * 8, sz);
            cp16z(so + 3 * HTILE + off,     pBl + j * 8, sz);
        }
        CP_COMMIT();
    };

    const int rsel = lid & 15, csel = lid >> 4;
    const int nch = KDIM / KC;     // 144
    prefetch(0, 0);
    prefetch(1, 1);
    int st = 0;
    for (int c = 0; c < nch; c++) {
        if (c + 2 < nch) { prefetch(c + 2, (st + 2) % HSTAGES); CP_WAIT2(); }
        else if (c + 1 < nch) { CP_WAIT1(); }
        else { CP_WAIT0(); }
        __syncthreads();
        for (int s = 0; s < 2; s++) { MMA_STEP_BODY(dsm_u32 + st * HSTAGE) }
        __syncthreads();
        st = (st + 1 == HSTAGES) ? 0 : st + 1;
    }

    const int rg = lid >> 2;
    const int cg = (lid & 3) * 2;
#pragma unroll
    for (int am = 0; am < 4; am++)
#pragma unroll
        for (int g = 0; g < 4; g++) {
            int row = bm + m0 + am * 16 + rg;
            int col = bn + n0 + g * 8 + cg;
            float* p0 = C + ((long)row << 10) + col;
            *(float2*)p0 = make_float2(acc[am][g][0], acc[am][g][1]);
            float* p1 = p0 + (8 << 10);
            *(float2*)p1 = make_float2(acc[am][g][2], acc[am][g][3]);
        }
}

// ============ generic NT HMMA GEMM (unchanged from R14) ====================
__global__ __launch_bounds__(256, 2)
void hmma_nt_kernel(const __nv_bfloat16* __restrict__ Ahg,
                    const __nv_bfloat16* __restrict__ Alg,
                    const __nv_bfloat16* __restrict__ Bhg,
                    const __nv_bfloat16* __restrict__ Blg,
                    float* __restrict__ Cg,
                    int M, int N, int K,
                    long sA, long sB, long sC, float alpha) {
    extern __shared__ char dsm_raw[];
    char* dsm = (char*)(((uintptr_t)dsm_raw + 1023) & ~(uintptr_t)1023);
    const uint32_t dsm_u32 = smem_to_u32(dsm);

    const int tid = threadIdx.x;
    const int wid = tid >> 5;
    const int lid = tid & 31;
    const int m0 = (wid >> 2) * 64;
    const int n0 = (wid & 3) * 32;
    const int bm = blockIdx.y * 128;
    const int bn = blockIdx.x * 128;
    const int b  = blockIdx.z;

    const __nv_bfloat16* Ah = Ahg + (long)b * sA;
    const __nv_bfloat16* Al = Alg + (long)b * sA;
    const __nv_bfloat16* Bh = Bhg + (long)b * sB;
    const __nv_bfloat16* Bl = Blg + (long)b * sB;
    float* C = Cg + (long)b * sC;

    const int frow = tid >> 1;
    const int fhalf = tid & 1;

    float acc[4][4][4];
#pragma unroll
    for (int i = 0; i < 4; i++)
#pragma unroll
        for (int j = 0; j < 4; j++)
#pragma unroll
            for (int q = 0; q < 4; q++) acc[i][j][q] = 0.f;

    auto prefetch = [&](int c, int st) {
        const long kb = (long)c * KC + fhalf * 16;
        const uint32_t so = dsm_u32 + st * HSTAGE;
        const __nv_bfloat16* pAh = Ah + (long)(bm + frow) * K + kb;
        const __nv_bfloat16* pAl = Al + (long)(bm + frow) * K + kb;
        const __nv_bfloat16* pBh = Bh + (long)(bn + frow) * K + kb;
        const __nv_bfloat16* pBl = Bl + (long)(bn + frow) * K + kb;
#pragma unroll
        for (int j = 0; j < 2; j++) {
            int chunk = fhalf * 2 + j;
            uint32_t off = frow * 64 + (((chunk ^ ((frow >> 1) & 3))) << 4);
            cp16(so + off,              pAh + j * 8);
            cp16(so + HTILE + off,      pAl + j * 8);
            cp16(so + 2 * HTILE + off,  pBh + j * 8);
            cp16(so + 3 * HTILE + off,  pBl + j * 8);
        }
        CP_COMMIT();
    };

    const int rsel = lid & 15, csel = lid >> 4;
    const int nch = K / KC;
    prefetch(0, 0);
    if (nch > 1) prefetch(1, 1);
    int st = 0;
    for (int c = 0; c < nch; c++) {
        if (c + 2 < nch) { prefetch(c + 2, (st + 2) % HSTAGES); CP_WAIT2(); }
        else if (c + 1 < nch) { CP_WAIT1(); }
        else { CP_WAIT0(); }
        __syncthreads();
        for (int s = 0; s < 2; s++) { MMA_STEP_BODY(dsm_u32 + st * HSTAGE) }
        __syncthreads();
        st = (st + 1 == HSTAGES) ? 0 : st + 1;
    }

    const int rg = lid >> 2;
    const int cg = (lid & 3) * 2;
#pragma unroll
    for (int am = 0; am < 4; am++)
#pragma unroll
        for (int g = 0; g < 4; g++) {
            int row = bm + m0 + am * 16 + rg;
            int col = bn + n0 + g * 8 + cg;
            float* p0 = C + (long)row * N + col;
            *(float2*)p0 = make_float2(alpha * acc[am][g][0], alpha * acc[am][g][1]);
            float* p1 = p0 + (long)8 * N;
            *(float2*)p1 = make_float2(alpha * acc[am][g][2], alpha * acc[am][g][3]);
        }
}

// ---------------- random_map = weight1 @ weight2^T -------------------------
__global__ void rmap_kernel(const float* __restrict__ w1,
                            const float* __restrict__ w2,
                            float* __restrict__ rm) {
    int idx = blockIdx.x * 256 + threadIdx.x;
    int i = idx >> 9, j = idx & 511;
    float s = 0.f;
#pragma unroll
    for (int k = 0; k < 16; k++) s += w1[i * 16 + k] * w2[j * 16 + k];
    rm[idx] = s;
}

// ---------------- row softmax over 512, with random_map added --------------
__global__ void softmax_kernel(float* __restrict__ S, const float* __restrict__ rmap) {
    const int c = blockIdx.x, b = blockIdx.y;
    float* row = S + ((long)b * CC + c) * CC;
    const float* rm = rmap + (long)c * CC;
    const int t = threadIdx.x;
    __shared__ float smax[4], ssum[4];
    float v[4];
#pragma unroll
    for (int j = 0; j < 4; j++) v[j] = row[t + 128 * j] + rm[t + 128 * j];
    float m = fmaxf(fmaxf(v[0], v[1]), fmaxf(v[2], v[3]));
    for (int o = 16; o; o >>= 1) m = fmaxf(m, __shfl_xor_sync(0xffffffffu, m, o));
    if ((t & 31) == 0) smax[t >> 5] = m;
    __syncthreads();
    m = fmaxf(fmaxf(smax[0], smax[1]), fmaxf(smax[2], smax[3]));
    float e[4], s = 0.f;
#pragma unroll
    for (int j = 0; j < 4; j++) { e[j] = __expf(v[j] - m); s += e[j]; }
    for (int o = 16; o; o >>= 1) s += __shfl_xor_sync(0xffffffffu, s, o);
    if ((t & 31) == 0) ssum[t >> 5] = s;
    __syncthreads();
    s = ssum[0] + ssum[1] + ssum[2] + ssum[3];
    float inv = 1.0f / s;
#pragma unroll
    for (int j = 0; j < 4; j++) row[t + 128 * j] = e[j] * inv;
}

// ---------------- launch ---------------------------------------------------
extern "C" void kernel_launch(void* const* d_in, const int* in_sizes, int n_in,
                              void* d_out, int out_size) {
    const float* x1  = (const float*)d_in[0];
    const float* x2  = (const float*)d_in[1];
    const float* g_w = (const float*)d_in[2];
    const float* w_w = (const float*)d_in[3];
    const float* w1  = (const float*)d_in[4];
    const float* w2  = (const float*)d_in[5];
    float* out = (float*)d_out;

    __nv_bfloat16 *xh, *xl, *xth, *xtl, *wh, *wl;
    __nv_bfloat16 *ath, *atl, *vth, *vtl, *th, *tl, *wwh, *wwl;
    float *value, *attn, *rmap, *T;
    cudaGetSymbolAddress((void**)&xh, g_xh);
    cudaGetSymbolAddress((void**)&xl, g_xl);
    cudaGetSymbolAddress((void**)&xth, g_xth);
    cudaGetSymbolAddress((void**)&xtl, g_xtl);
    cudaGetSymbolAddress((void**)&wh, g_wh);
    cudaGetSymbolAddress((void**)&wl, g_wl);
    cudaGetSymbolAddress((void**)&ath, g_ath);
    cudaGetSymbolAddress((void**)&atl, g_atl);
    cudaGetSymbolAddress((void**)&vth, g_vth);
    cudaGetSymbolAddress((void**)&vtl, g_vtl);
    cudaGetSymbolAddress((void**)&th, g_th);
    cudaGetSymbolAddress((void**)&tl, g_tl);
    cudaGetSymbolAddress((void**)&wwh, g_wwh);
    cudaGetSymbolAddress((void**)&wwl, g_wwl);
    cudaGetSymbolAddress((void**)&value, g_value);
    cudaGetSymbolAddress((void**)&attn,  g_attn);
    cudaGetSymbolAddress((void**)&rmap,  g_rmap);
    cudaGetSymbolAddress((void**)&T,     g_T);

    cudaFuncSetAttribute(hmma_nt_kernel,
                         cudaFuncAttributeMaxDynamicSharedMemorySize, HDSMEM);
    cudaFuncSetAttribute(conv_hmma_kernel,
                         cudaFuncAttributeMaxDynamicSharedMemorySize, HDSMEM);

    // 1. concat + split -> X (channel-major, for sim)
    concat_split_kernel<<<BATCH * CC * 256 / 256, 256>>>(
        (const float4*)x1, (const float4*)x2, xh, xl);

    // 2. concat + transpose + split -> X^T (spatial-major, for conv B)
    {
        dim3 grid(HW / 32, CC / 32, BATCH);
        xt_split_kernel<<<grid, dim3(32, 8)>>>(x1, x2, xth, xtl);
    }

    // 3. weight permute+split (k=(t,ci)) and w_w split
    wperm_split_kernel<<<(CC * KDIM) / 256, 256>>>(g_w, wh, wl);
    fsplit_kernel<<<(CO * CC / 4) / 256, 256>>>((const float4*)w_w, wwh, wwl);

    // 4. value = conv3x3(x): HMMA with shifted-X^T B operand (no im2col)
    {
        dim3 grid(HW / 128, CC / 128, BATCH);
        conv_hmma_kernel<<<grid, 256, HDSMEM>>>(wh, wl, xth, xtl, value);
    }

    // 5. random_map
    rmap_kernel<<<(CC * CC) / 256, 256>>>(w1, w2, rmap);

    // 6. sim = (q @ q^T) * c^-0.5
    {
        dim3 grid(CC / 128, CC / 128, BATCH);
        hmma_nt_kernel<<<grid, 256, HDSMEM>>>(xh, xl, xh, xl, attn,
                                              CC, CC, HW,
                                              (long)CC * HW, (long)CC * HW,
                                              (long)CC * CC,
                                              1.0f / sqrtf((float)CC));
    }

    // 7. softmax(sim + rmap) in place
    {
        dim3 grid(CC, BATCH);
        softmax_kernel<<<grid, 128>>>(attn, rmap);
    }

    // 8a. attn^T split
    {
        dim3 grid(CC / 32, CC / 32, BATCH);
        tsplit_kernel<<<grid, dim3(32, 8)>>>(attn, ath, atl, CC, CC,
                                             (long)CC * CC, (long)CC * CC);
    }
    // 8b. value^T split
    {
        dim3 grid(HW / 32, CC / 32, BATCH);
        tsplit_kernel<<<grid, dim3(32, 8)>>>(value, vth, vtl, CC, HW,
                                             (long)CC * HW, (long)CC * HW);
    }

    // 8c. T = w_w @ attn
    {
        dim3 grid(CC / 128, CO / 128, BATCH);
        hmma_nt_kernel<<<grid, 256, HDSMEM>>>(wwh, wwl, ath, atl, T,
                                              CO, CC, CC,
                                              0L, (long)CC * CC,
                                              (long)CO * CC, 1.0f);
    }

    // 8d. T split
    fsplit_kernel<<<(BATCH * CO * CC / 4) / 256, 256>>>((const float4*)T, th, tl);

    // 9. out = T @ value
    {
        dim3 grid(HW / 128, CO / 128, BATCH);
        hmma_nt_kernel<<<grid, 256, HDSMEM>>>(th, tl, vth, vtl, out,
                                              CO, HW, CC,
                                              (long)CO * CC, (long)HW * CC,
                                              (long)CO * HW, 1.0f);
    }
}

// round 16
// speedup vs baseline: 2.5034x; 1.0764x over previous
#include <cuda_runtime.h>
#include <cuda_bf16.h>
#include <math.h>
#include <stdint.h>

// Problem constants
#define BATCH 16
#define CH    256
#define CC    512
#define HW    1024
#define KDIM  (CC * 9)     // 4608
#define CO    256

// ---------------- scratch (device globals: allocation-free) ----------------
__device__ __nv_bfloat16 g_xh [BATCH * CC * HW];    // X [b][c][n] hi (sim)
__device__ __nv_bfloat16 g_xl [BATCH * CC * HW];
__device__ __nv_bfloat16 g_xth[BATCH * HW * CC];    // X^T [b][n][c] (conv B)
__device__ __nv_bfloat16 g_xtl[BATCH * HW * CC];
__device__ __nv_bfloat16 g_wh [CC * KDIM];          // W permuted k=(t,ci)
__device__ __nv_bfloat16 g_wl [CC * KDIM];
__device__ __nv_bfloat16 g_vh [BATCH * CC * HW];    // value rows bf16 hi/lo
__device__ __nv_bfloat16 g_vl [BATCH * CC * HW];
__device__ float g_attn [BATCH * CC * CC];          // sim fp32 (softmax input)
__device__ float g_rmap [CC * CC];
__device__ __nv_bfloat16 g_ah [BATCH * CC * CC];    // attn rows bf16 hi/lo
__device__ __nv_bfloat16 g_al [BATCH * CC * CC];
__device__ __nv_bfloat16 g_th [BATCH * CO * CC];    // T rows bf16 hi/lo
__device__ __nv_bfloat16 g_tl [BATCH * CO * CC];
__device__ __nv_bfloat16 g_wwh[CO * CC];
__device__ __nv_bfloat16 g_wwl[CO * CC];

__device__ __forceinline__ uint32_t smem_to_u32(const void* p) {
    uint32_t a;
    asm("{ .reg .u64 t; cvta.to.shared.u64 t, %1; cvt.u32.u64 %0, t; }"
        : "=r"(a) : "l"(p));
    return a;
}

// ---------------- warp-mma building blocks ---------------------------------
#define LDSM_X4(R, ADDR) \
    asm volatile("ldmatrix.sync.aligned.m8n8.x4.shared.b16 {%0,%1,%2,%3}, [%4];" \
        : "=r"((R)[0]), "=r"((R)[1]), "=r"((R)[2]), "=r"((R)[3]) : "r"(ADDR))

#define LDSM_X4_T(R, ADDR) \
    asm volatile("ldmatrix.sync.aligned.m8n8.x4.trans.shared.b16 {%0,%1,%2,%3}, [%4];" \
        : "=r"((R)[0]), "=r"((R)[1]), "=r"((R)[2]), "=r"((R)[3]) : "r"(ADDR))

#define MMA16816(D, A, B0, B1) \
    asm volatile("mma.sync.aligned.m16n8k16.row.col.f32.bf16.bf16.f32 " \
        "{%0,%1,%2,%3}, {%4,%5,%6,%7}, {%8,%9}, {%0,%1,%2,%3};" \
        : "+f"((D)[0]), "+f"((D)[1]), "+f"((D)[2]), "+f"((D)[3]) \
        : "r"((A)[0]), "r"((A)[1]), "r"((A)[2]), "r"((A)[3]), "r"(B0), "r"(B1))

__device__ __forceinline__ void cp16(uint32_t s, const void* g) {
    asm volatile("cp.async.cg.shared.global [%0], [%1], 16;" :: "r"(s), "l"(g));
}
__device__ __forceinline__ void cp16z(uint32_t s, const void* g, uint32_t sz) {
    asm volatile("cp.async.cg.shared.global [%0], [%1], 16, %2;"
                 :: "r"(s), "l"(g), "r"(sz));
}
#define CP_COMMIT() asm volatile("cp.async.commit_group;" ::: "memory")
#define CP_WAIT1()  asm volatile("cp.async.wait_group 1;" ::: "memory")
#define CP_WAIT0()  asm volatile("cp.async.wait_group 0;" ::: "memory")

__device__ __forceinline__ void split2(float x, float y, uint32_t& hi, uint32_t& lo) {
    __nv_bfloat16 hx = __float2bfloat16(x), hy = __float2bfloat16(y);
    __nv_bfloat16 lx = __float2bfloat16(x - __bfloat162float(hx));
    __nv_bfloat16 ly = __float2bfloat16(y - __bfloat162float(hy));
    hi = ((uint32_t)__bfloat16_as_ushort(hy) << 16) | __bfloat16_as_ushort(hx);
    lo = ((uint32_t)__bfloat16_as_ushort(ly) << 16) | __bfloat16_as_ushort(lx);
}

// ============ prep kernels =================================================
__global__ void concat_split_kernel(const float4* __restrict__ x1,
                                    const float4* __restrict__ x2,
                                    __nv_bfloat16* __restrict__ xh,
                                    __nv_bfloat16* __restrict__ xl) {
    int idx = blockIdx.x * 256 + threadIdx.x;
    int p = idx & 255;
    int c = (idx >> 8) & 511;
    int b = idx >> 17;
    float4 v = (c < CH) ? x1[((b << 8) + c) * 256 + p]
                        : x2[((b << 8) + (c - CH)) * 256 + p];
    uint32_t h0, l0, h1, l1;
    split2(v.x, v.y, h0, l0);
    split2(v.z, v.w, h1, l1);
    *(uint2*)(xh + (size_t)idx * 4) = make_uint2(h0, h1);
    *(uint2*)(xl + (size_t)idx * 4) = make_uint2(l0, l1);
}

__global__ void xt_split_kernel(const float* __restrict__ x1,
                                const float* __restrict__ x2,
                                __nv_bfloat16* __restrict__ oh,
                                __nv_bfloat16* __restrict__ ol) {
    __shared__ float t[32][33];
    int b = blockIdx.z;
    int c0 = blockIdx.y * 32, n0 = blockIdx.x * 32;
    int tx = threadIdx.x, ty = threadIdx.y;     // 32 x 8
    const float* src = (c0 < CH) ? (x1 + ((long)b * CH + c0) * HW)
                                 : (x2 + ((long)b * CH + (c0 - CH)) * HW);
#pragma unroll
    for (int j = 0; j < 4; j++)
        t[ty + 8 * j][tx] = src[(long)(ty + 8 * j) * HW + n0 + tx];
    __syncthreads();
    __nv_bfloat16* oph = oh + (long)b * HW * CC;
    __nv_bfloat16* opl = ol + (long)b * HW * CC;
#pragma unroll
    for (int j = 0; j < 4; j++) {
        float v = t[tx][ty + 8 * j];
        __nv_bfloat16 h = __float2bfloat16(v);
        __nv_bfloat16 l = __float2bfloat16(v - __bfloat162float(h));
        long o = (long)(n0 + ty + 8 * j) * CC + c0 + tx;
        oph[o] = h; opl[o] = l;
    }
}

__global__ void wperm_split_kernel(const float* __restrict__ w,
                                   __nv_bfloat16* __restrict__ wh,
                                   __nv_bfloat16* __restrict__ wl) {
    int idx = blockIdx.x * 256 + threadIdx.x;   // 512*4608
    int k = idx % KDIM;
    int m = idx / KDIM;
    int t = k >> 9, ci = k & 511;
    float v = w[(long)m * KDIM + ci * 9 + t];
    __nv_bfloat16 h = __float2bfloat16(v);
    __nv_bfloat16 l = __float2bfloat16(v - __bfloat162float(h));
    wh[idx] = h; wl[idx] = l;
}

__global__ void fsplit_kernel(const float4* __restrict__ w,
                              __nv_bfloat16* __restrict__ wh,
                              __nv_bfloat16* __restrict__ wl) {
    int idx = blockIdx.x * 256 + threadIdx.x;
    float4 v = w[idx];
    uint32_t h0, l0, h1, l1;
    split2(v.x, v.y, h0, l0);
    split2(v.z, v.w, h1, l1);
    *(uint2*)(wh + (size_t)idx * 4) = make_uint2(h0, h1);
    *(uint2*)(wl + (size_t)idx * 4) = make_uint2(l0, l1);
}

// ============ shared GEMM config ===========================================
#define KC       32
#define HTILE    8192                  // A: 128 rows x 64B | B: 32 rows x 256B
#define HSTAGE   (4 * HTILE)           // Ah, Al, Bh, Bl = 32 KB
#define HSTAGES  3
#define HDSMEM   (1024 + HSTAGES * HSTAGE)

// ---- MMA inner step (A fragments NT; B per layout) ----
#define MMA_CORE(AH, AL, BH, BL)                                               \
    _Pragma("unroll")                                                          \
    for (int am = 0; am < 4; am++)                                             \
        _Pragma("unroll")                                                      \
        for (int g = 0; g < 4; g++) {                                          \
            int bi = g >> 1, u = g & 1;                                        \
            MMA16816(acc[am][g], AH[am], BH[bi][u], BH[bi][u + 2]);            \
        }                                                                      \
    _Pragma("unroll")                                                          \
    for (int am = 0; am < 4; am++)                                             \
        _Pragma("unroll")                                                      \
        for (int g = 0; g < 4; g++) {                                          \
            int bi = g >> 1, u = g & 1;                                        \
            MMA16816(acc[am][g], AH[am], BL[bi][u], BL[bi][u + 2]);            \
        }                                                                      \
    _Pragma("unroll")                                                          \
    for (int am = 0; am < 4; am++)                                             \
        _Pragma("unroll")                                                      \
        for (int g = 0; g < 4; g++) {                                          \
            int bi = g >> 1, u = g & 1;                                        \
            MMA16816(acc[am][g], AL[am], BH[bi][u], BH[bi][u + 2]);            \
        }

// ============ generic HMMA GEMM ============================================
// NN=0: B global [N][K] (k-major per n-row). NN=1: B global [K][N] rows.
// EPI=0: fp32 out (alpha). EPI=1: bf16 hi/lo split out (alpha).
template<int NN, int EPI>
__global__ __launch_bounds__(256, 2)
void hmma_kernel(const __nv_bfloat16* __restrict__ Ahg,
                 const __nv_bfloat16* __restrict__ Alg,
                 const __nv_bfloat16* __restrict__ Bhg,
                 const __nv_bfloat16* __restrict__ Blg,
                 float* __restrict__ Cf,
                 __nv_bfloat16* __restrict__ Ch,
                 __nv_bfloat16* __restrict__ Cl,
                 int M, int N, int K,
                 long sA, long sB, long sC, float alpha) {
    extern __shared__ char dsm_raw[];
    char* dsm = (char*)(((uintptr_t)dsm_raw + 1023) & ~(uintptr_t)1023);
    const uint32_t dsm_u32 = smem_to_u32(dsm);

    const int tid = threadIdx.x;
    const int wid = tid >> 5;
    const int lid = tid & 31;
    const int m0 = (wid >> 2) * 64;
    const int n0 = (wid & 3) * 32;
    const int bm = blockIdx.y * 128;
    const int bn = blockIdx.x * 128;
    const int b  = blockIdx.z;

    const __nv_bfloat16* Ah = Ahg + (long)b * sA;
    const __nv_bfloat16* Al = Alg + (long)b * sA;
    const __nv_bfloat16* Bh = Bhg + (long)b * sB;
    const __nv_bfloat16* Bl = Blg + (long)b * sB;

    const int frow = tid >> 1;
    const int fhalf = tid & 1;

    float acc[4][4][4];
#pragma unroll
    for (int i = 0; i < 4; i++)
#pragma unroll
        for (int j = 0; j < 4; j++)
#pragma unroll
            for (int q = 0; q < 4; q++) acc[i][j][q] = 0.f;

    auto prefetch = [&](int c, int st) {
        const uint32_t so = dsm_u32 + st * HSTAGE;
        const long kb = (long)c * KC + fhalf * 16;
        const __nv_bfloat16* pAh = Ah + (long)(bm + frow) * K + kb;
        const __nv_bfloat16* pAl = Al + (long)(bm + frow) * K + kb;
#pragma unroll
        for (int j = 0; j < 2; j++) {
            int chunk = fhalf * 2 + j;
            uint32_t off = frow * 64 + (((chunk ^ ((frow >> 1) & 3))) << 4);
            cp16(so + off,          pAh + j * 8);
            cp16(so + HTILE + off,  pAl + j * 8);
        }
        if (NN == 0) {
            const __nv_bfloat16* pBh = Bh + (long)(bn + frow) * K + kb;
            const __nv_bfloat16* pBl = Bl + (long)(bn + frow) * K + kb;
#pragma unroll
            for (int j = 0; j < 2; j++) {
                int chunk = fhalf * 2 + j;
                uint32_t off = frow * 64 + (((chunk ^ ((frow >> 1) & 3))) << 4);
                cp16(so + 2 * HTILE + off, pBh + j * 8);
                cp16(so + 3 * HTILE + off, pBl + j * 8);
            }
        } else {
            // B tile: 32 k-rows x 256B (128 n bf16)
#pragma unroll
            for (int j = 0; j < 2; j++) {
                int u = tid + 256 * j;          // 0..511
                int row = u >> 4;               // k-row
                int ch  = u & 15;               // 16B n-chunk
                const long gb = (long)(c * KC + row) * N + bn + ch * 8;
                uint32_t off = row * 256 + (((ch ^ (row & 7))) << 4);
                cp16(so + 2 * HTILE + off, Bh + gb);
                cp16(so + 3 * HTILE + off, Bl + gb);
            }
        }
        CP_COMMIT();
    };

    const int rsel = lid & 15, csel = lid >> 4;
    auto mma_step = [&](int st, int s) {
        const uint32_t base = dsm_u32 + st * HSTAGE;
        uint32_t ah[4][4], al[4][4], bh2[2][4], bl2[2][4];
#pragma unroll
        for (int am = 0; am < 4; am++) {
            int row = m0 + am * 16 + rsel;
            uint32_t off = row * 64 + ((((2 * s + csel) ^ ((row >> 1) & 3))) << 4);
            LDSM_X4(ah[am], base + off);
            LDSM_X4(al[am], base + HTILE + off);
        }
        if (NN == 0) {
#pragma unroll
            for (int bi = 0; bi < 2; bi++) {
                int row = n0 + bi * 16 + rsel;
                uint32_t off = row * 64 + ((((2 * s + csel) ^ ((row >> 1) & 3))) << 4);
                LDSM_X4(bh2[bi], base + 2 * HTILE + off);
                LDSM_X4(bl2[bi], base + 3 * HTILE + off);
            }
        } else {
            // trans ldmatrix: lanes 0-7:(k0-7,nchA) 8-15:(k0-7,nchA+1)
            //                 16-23:(k8-15,nchA) 24-31:(k8-15,nchA+1)
            int krow = s * 16 + ((lid >> 4) << 3) + (lid & 7);
#pragma unroll
            for (int bi = 0; bi < 2; bi++) {
                int nch = (n0 >> 3) + bi * 2 + ((lid >> 3) & 1);
                uint32_t off = krow * 256 + (((nch ^ (krow & 7))) << 4);
                LDSM_X4_T(bh2[bi], base + 2 * HTILE + off);
                LDSM_X4_T(bl2[bi], base + 3 * HTILE + off);
            }
        }
        MMA_CORE(ah, al, bh2, bl2)
    };

    const int nch = K / KC;
    prefetch(0, 0);
    prefetch(1, 1);
    int st = 0;
    for (int c = 0; c < nch; c++) {
        if (c + 2 < nch) CP_WAIT1(); else CP_WAIT0();
        __syncthreads();
        mma_step(st, 0);
        mma_step(st, 1);
        if (c + 2 < nch) prefetch(c + 2, (st + 2) % HSTAGES);
        st = (st + 1 == HSTAGES) ? 0 : st + 1;
    }

    const int rg = lid >> 2;
    const int cg = (lid & 3) * 2;
#pragma unroll
    for (int am = 0; am < 4; am++)
#pragma unroll
        for (int g = 0; g < 4; g++) {
            int row = bm + m0 + am * 16 + rg;
            int col = bn + n0 + g * 8 + cg;
            float v0 = alpha * acc[am][g][0], v1 = alpha * acc[am][g][1];
            float v2 = alpha * acc[am][g][2], v3 = alpha * acc[am][g][3];
            if (EPI == 0) {
                float* p0 = Cf + (long)b * sC + (long)row * N + col;
                *(float2*)p0 = make_float2(v0, v1);
                *(float2*)(p0 + (long)8 * N) = make_float2(v2, v3);
            } else {
                uint32_t h, l;
                long o0 = (long)b * sC + (long)row * N + col;
                long o1 = o0 + (long)8 * N;
                split2(v0, v1, h, l);
                *(uint32_t*)(Ch + o0) = h; *(uint32_t*)(Cl + o0) = l;
                split2(v2, v3, h, l);
                *(uint32_t*)(Ch + o1) = h; *(uint32_t*)(Cl + o1) = l;
            }
        }
}

// ============ conv GEMM: B = shifted X^T (fused im2col), bf16 split out ====
__global__ __launch_bounds__(256, 2)
void conv_hmma_kernel(const __nv_bfloat16* __restrict__ Wh,
                      const __nv_bfloat16* __restrict__ Wl,
                      const __nv_bfloat16* __restrict__ XTh,
                      const __nv_bfloat16* __restrict__ XTl,
                      __nv_bfloat16* __restrict__ Vh,
                      __nv_bfloat16* __restrict__ Vl) {
    extern __shared__ char dsm_raw[];
    char* dsm = (char*)(((uintptr_t)dsm_raw + 1023) & ~(uintptr_t)1023);
    const uint32_t dsm_u32 = smem_to_u32(dsm);

    const int tid = threadIdx.x;
    const int wid = tid >> 5;
    const int lid = tid & 31;
    const int m0 = (wid >> 2) * 64;
    const int n0 = (wid & 3) * 32;
    const int bm = blockIdx.y * 128;
    const int bn = blockIdx.x * 128;
    const int b  = blockIdx.z;

    const __nv_bfloat16* Bh = XTh + (long)b * HW * CC;
    const __nv_bfloat16* Bl = XTl + (long)b * HW * CC;

    const int frow = tid >> 1;
    const int fhalf = tid & 1;
    const int sp = bn + frow;
    const int sy = sp >> 5, sx = sp & 31;

    float acc[4][4][4];
#pragma unroll
    for (int i = 0; i < 4; i++)
#pragma unroll
        for (int j = 0; j < 4; j++)
#pragma unroll
            for (int q = 0; q < 4; q++) acc[i][j][q] = 0.f;

    auto prefetch = [&](int c, int st) {
        const uint32_t so = dsm_u32 + st * HSTAGE;
        const long kb = (long)c * KC + fhalf * 16;
        const __nv_bfloat16* pAh = Wh + (long)(bm + frow) * KDIM + kb;
        const __nv_bfloat16* pAl = Wl + (long)(bm + frow) * KDIM + kb;
        const int t = c >> 4;
        const int dy = (t >= 6) ? 1 : ((t >= 3) ? 0 : -1);
        const int dx = t - (dy + 1) * 3 - 1;
        const int y = sy + dy, x = sx + dx;
        const bool ok = ((unsigned)y < 32u) & ((unsigned)x < 32u);
        const uint32_t sz = ok ? 16u : 0u;
        const long bsrc = ok ? ((long)((y << 5) + x) * CC + (c & 15) * 32 + fhalf * 16)
                             : 0L;
#pragma unroll
        for (int j = 0; j < 2; j++) {
            int chunk = fhalf * 2 + j;
            uint32_t off = frow * 64 + (((chunk ^ ((frow >> 1) & 3))) << 4);
            cp16(so + off,              pAh + j * 8);
            cp16(so + HTILE + off,      pAl + j * 8);
            cp16z(so + 2 * HTILE + off, Bh + bsrc + j * 8, sz);
            cp16z(so + 3 * HTILE + off, Bl + bsrc + j * 8, sz);
        }
        CP_COMMIT();
    };

    const int rsel = lid & 15, csel = lid >> 4;
    auto mma_step = [&](int st, int s) {
        const uint32_t base = dsm_u32 + st * HSTAGE;
        uint32_t ah[4][4], al[4][4], bh2[2][4], bl2[2][4];
#pragma unroll
        for (int am = 0; am < 4; am++) {
            int row = m0 + am * 16 + rsel;
            uint32_t off = row * 64 + ((((2 * s + csel) ^ ((row >> 1) & 3))) << 4);
            LDSM_X4(ah[am], base + off);
            LDSM_X4(al[am], base + HTILE + off);
        }
#pragma unroll
        for (int bi = 0; bi < 2; bi++) {
            int row = n0 + bi * 16 + rsel;
            uint32_t off = row * 64 + ((((2 * s + csel) ^ ((row >> 1) & 3))) << 4);
            LDSM_X4(bh2[bi], base + 2 * HTILE + off);
            LDSM_X4(bl2[bi], base + 3 * HTILE + off);
        }
        MMA_CORE(ah, al, bh2, bl2)
    };

    const int nch = KDIM / KC;     // 144
    prefetch(0, 0);
    prefetch(1, 1);
    int st = 0;
    for (int c = 0; c < nch; c++) {
        if (c + 2 < nch) CP_WAIT1(); else CP_WAIT0();
        __syncthreads();
        mma_step(st, 0);
        mma_step(st, 1);
        if (c + 2 < nch) prefetch(c + 2, (st + 2) % HSTAGES);
        st = (st + 1 == HSTAGES) ? 0 : st + 1;
    }

    const int rg = lid >> 2;
    const int cg = (lid & 3) * 2;
#pragma unroll
    for (int am = 0; am < 4; am++)
#pragma unroll
        for (int g = 0; g < 4; g++) {
            int row = bm + m0 + am * 16 + rg;
            int col = bn + n0 + g * 8 + cg;
            long o0 = (((long)b * CC + row) << 10) + col;
            long o1 = o0 + (8 << 10);
            uint32_t h, l;
            split2(acc[am][g][0], acc[am][g][1], h, l);
            *(uint32_t*)(Vh + o0) = h; *(uint32_t*)(Vl + o0) = l;
            split2(acc[am][g][2], acc[am][g][3], h, l);
            *(uint32_t*)(Vh + o1) = h; *(uint32_t*)(Vl + o1) = l;
        }
}

// ---------------- random_map = weight1 @ weight2^T -------------------------
__global__ void rmap_kernel(const float* __restrict__ w1,
                            const float* __restrict__ w2,
                            float* __restrict__ rm) {
    int idx = blockIdx.x * 256 + threadIdx.x;
    int i = idx >> 9, j = idx & 511;
    float s = 0.f;
#pragma unroll
    for (int k = 0; k < 16; k++) s += w1[i * 16 + k] * w2[j * 16 + k];
    rm[idx] = s;
}

// ---------------- softmax over 512 + rmap; writes bf16 hi/lo rows ----------
__global__ void softmax_kernel(const float* __restrict__ S,
                               const float* __restrict__ rmap,
                               __nv_bfloat16* __restrict__ oh,
                               __nv_bfloat16* __restrict__ ol) {
    const int c = blockIdx.x, b = blockIdx.y;
    const float* row = S + ((long)b * CC + c) * CC;
    const float* rm = rmap + (long)c * CC;
    const int t = threadIdx.x;
    __shared__ float smax[4], ssum[4];
    float v[4];
#pragma unroll
    for (int j = 0; j < 4; j++) v[j] = row[t + 128 * j] + rm[t + 128 * j];
    float m = fmaxf(fmaxf(v[0], v[1]), fmaxf(v[2], v[3]));
    for (int o = 16; o; o >>= 1) m = fmaxf(m, __shfl_xor_sync(0xffffffffu, m, o));
    if ((t & 31) == 0) smax[t >> 5] = m;
    __syncthreads();
    m = fmaxf(fmaxf(smax[0], smax[1]), fmaxf(smax[2], smax[3]));
    float e[4], s = 0.f;
#pragma unroll
    for (int j = 0; j < 4; j++) { e[j] = __expf(v[j] - m); s += e[j]; }
    for (int o = 16; o; o >>= 1) s += __shfl_xor_sync(0xffffffffu, s, o);
    if ((t & 31) == 0) ssum[t >> 5] = s;
    __syncthreads();
    s = ssum[0] + ssum[1] + ssum[2] + ssum[3];
    float inv = 1.0f / s;
    __nv_bfloat16* ph = oh + ((long)b * CC + c) * CC;
    __nv_bfloat16* pl = ol + ((long)b * CC + c) * CC;
#pragma unroll
    for (int j = 0; j < 4; j++) {
        float x = e[j] * inv;
        __nv_bfloat16 h = __float2bfloat16(x);
        __nv_bfloat16 l = __float2bfloat16(x - __bfloat162float(h));
        ph[t + 128 * j] = h; pl[t + 128 * j] = l;
    }
}

// ---------------- launch ---------------------------------------------------
extern "C" void kernel_launch(void* const* d_in, const int* in_sizes, int n_in,
                              void* d_out, int out_size) {
    const float* x1  = (const float*)d_in[0];
    const float* x2  = (const float*)d_in[1];
    const float* g_w = (const float*)d_in[2];
    const float* w_w = (const float*)d_in[3];
    const float* w1  = (const float*)d_in[4];
    const float* w2  = (const float*)d_in[5];
    float* out = (float*)d_out;

    __nv_bfloat16 *xh, *xl, *xth, *xtl, *wh, *wl, *vh, *vl;
    __nv_bfloat16 *ah, *al, *th, *tl, *wwh, *wwl;
    float *attn, *rmap;
    cudaGetSymbolAddress((void**)&xh, g_xh);
    cudaGetSymbolAddress((void**)&xl, g_xl);
    cudaGetSymbolAddress((void**)&xth, g_xth);
    cudaGetSymbolAddress((void**)&xtl, g_xtl);
    cudaGetSymbolAddress((void**)&wh, g_wh);
    cudaGetSymbolAddress((void**)&wl, g_wl);
    cudaGetSymbolAddress((void**)&vh, g_vh);
    cudaGetSymbolAddress((void**)&vl, g_vl);
    cudaGetSymbolAddress((void**)&ah, g_ah);
    cudaGetSymbolAddress((void**)&al, g_al);
    cudaGetSymbolAddress((void**)&th, g_th);
    cudaGetSymbolAddress((void**)&tl, g_tl);
    cudaGetSymbolAddress((void**)&wwh, g_wwh);
    cudaGetSymbolAddress((void**)&wwl, g_wwl);
    cudaGetSymbolAddress((void**)&attn, g_attn);
    cudaGetSymbolAddress((void**)&rmap, g_rmap);

    cudaFuncSetAttribute(conv_hmma_kernel,
                         cudaFuncAttributeMaxDynamicSharedMemorySize, HDSMEM);
    cudaFuncSetAttribute(hmma_kernel<0, 0>,
                         cudaFuncAttributeMaxDynamicSharedMemorySize, HDSMEM);
    cudaFuncSetAttribute(hmma_kernel<1, 0>,
                         cudaFuncAttributeMaxDynamicSharedMemorySize, HDSMEM);
    cudaFuncSetAttribute(hmma_kernel<1, 1>,
                         cudaFuncAttributeMaxDynamicSharedMemorySize, HDSMEM);

    // 1. concat + split -> X (channel-major, for sim)
    concat_split_kernel<<<BATCH * CC * 256 / 256, 256>>>(
        (const float4*)x1, (const float4*)x2, xh, xl);

    // 2. concat + transpose + split -> X^T (for conv B)
    {
        dim3 grid(HW / 32, CC / 32, BATCH);
        xt_split_kernel<<<grid, dim3(32, 8)>>>(x1, x2, xth, xtl);
    }

    // 3. weight permute+split and w_w split
    wperm_split_kernel<<<(CC * KDIM) / 256, 256>>>(g_w, wh, wl);
    fsplit_kernel<<<(CO * CC / 4) / 256, 256>>>((const float4*)w_w, wwh, wwl);

    // 4. value = conv3x3(x), bf16-split rows out (no fp32 value)
    {
        dim3 grid(HW / 128, CC / 128, BATCH);
        conv_hmma_kernel<<<grid, 256, HDSMEM>>>(wh, wl, xth, xtl, vh, vl);
    }

    // 5. random_map
    rmap_kernel<<<(CC * CC) / 256, 256>>>(w1, w2, rmap);

    // 6. sim = (q @ q^T) * c^-0.5  (NT, fp32 out)
    {
        dim3 grid(CC / 128, CC / 128, BATCH);
        hmma_kernel<0, 0><<<grid, 256, HDSMEM>>>(
            xh, xl, xh, xl, attn, nullptr, nullptr,
            CC, CC, HW, (long)CC * HW, (long)CC * HW, (long)CC * CC,
            1.0f / sqrtf((float)CC));
    }

    // 7. softmax(sim + rmap) -> attn bf16 hi/lo rows
    {
        dim3 grid(CC, BATCH);
        softmax_kernel<<<grid, 128>>>(attn, rmap, ah, al);
    }

    // 8. T = w_w @ attn  (NN: B = attn rows; bf16-split out)
    {
        dim3 grid(CC / 128, CO / 128, BATCH);
        hmma_kernel<1, 1><<<grid, 256, HDSMEM>>>(
            wwh, wwl, ah, al, nullptr, th, tl,
            CO, CC, CC, 0L, (long)CC * CC, (long)CO * CC, 1.0f);
    }

    // 9. out = T @ value  (NN: B = value rows; fp32 out)
    {
        dim3 grid(HW / 128, CO / 128, BATCH);
        hmma_kernel<1, 0><<<grid, 256, HDSMEM>>>(
            th, tl, vh, vl, out, nullptr, nullptr,
            CO, HW, CC, (long)CO * CC, (long)CC * HW, (long)CO * HW, 1.0f);
    }
}

// round 17
// speedup vs baseline: 4.6013x; 1.8380x over previous
#include <cuda_runtime.h>
#include <cuda_bf16.h>
#include <math.h>
#include <stdint.h>

// Problem constants
#define BATCH 16
#define CH    256
#define CC    512
#define HW    1024
#define CO    256
#define NTILE 256          // 16x16 winograd 2x2-output tiles per image

// ---------------- scratch (device globals: allocation-free) ----------------
__device__ __nv_bfloat16 g_xh [BATCH * CC * HW];            // X [b][c][n] (sim)
__device__ __nv_bfloat16 g_xl [BATCH * CC * HW];
__device__ __nv_bfloat16 g_uh [16 * CC * CC];               // U [t][co][ci]
__device__ __nv_bfloat16 g_ul [16 * CC * CC];
__device__ __nv_bfloat16 g_vwh[(size_t)BATCH * 16 * CC * NTILE]; // V [b][t][ci][tile]
__device__ __nv_bfloat16 g_vwl[(size_t)BATCH * 16 * CC * NTILE];
__device__ float g_m  [(size_t)BATCH * 16 * CC * NTILE];    // M [b][t][co][tile] fp32
__device__ __nv_bfloat16 g_vh [BATCH * CC * HW];            // value rows bf16
__device__ __nv_bfloat16 g_vl [BATCH * CC * HW];
__device__ float g_attn [BATCH * CC * CC];
__device__ float g_rmap [CC * CC];
__device__ __nv_bfloat16 g_ah [BATCH * CC * CC];            // attn rows bf16
__device__ __nv_bfloat16 g_al [BATCH * CC * CC];
__device__ __nv_bfloat16 g_th [BATCH * CO * CC];            // T rows bf16
__device__ __nv_bfloat16 g_tl [BATCH * CO * CC];
__device__ __nv_bfloat16 g_wwh[CO * CC];
__device__ __nv_bfloat16 g_wwl[CO * CC];

__device__ __forceinline__ uint32_t smem_to_u32(const void* p) {
    uint32_t a;
    asm("{ .reg .u64 t; cvta.to.shared.u64 t, %1; cvt.u32.u64 %0, t; }"
        : "=r"(a) : "l"(p));
    return a;
}

// ---------------- warp-mma building blocks ---------------------------------
#define LDSM_X4(R, ADDR) \
    asm volatile("ldmatrix.sync.aligned.m8n8.x4.shared.b16 {%0,%1,%2,%3}, [%4];" \
        : "=r"((R)[0]), "=r"((R)[1]), "=r"((R)[2]), "=r"((R)[3]) : "r"(ADDR))

#define LDSM_X4_T(R, ADDR) \
    asm volatile("ldmatrix.sync.aligned.m8n8.x4.trans.shared.b16 {%0,%1,%2,%3}, [%4];" \
        : "=r"((R)[0]), "=r"((R)[1]), "=r"((R)[2]), "=r"((R)[3]) : "r"(ADDR))

#define MMA16816(D, A, B0, B1) \
    asm volatile("mma.sync.aligned.m16n8k16.row.col.f32.bf16.bf16.f32 " \
        "{%0,%1,%2,%3}, {%4,%5,%6,%7}, {%8,%9}, {%0,%1,%2,%3};" \
        : "+f"((D)[0]), "+f"((D)[1]), "+f"((D)[2]), "+f"((D)[3]) \
        : "r"((A)[0]), "r"((A)[1]), "r"((A)[2]), "r"((A)[3]), "r"(B0), "r"(B1))

__device__ __forceinline__ void cp16(uint32_t s, const void* g) {
    asm volatile("cp.async.cg.shared.global [%0], [%1], 16;" :: "r"(s), "l"(g));
}
#define CP_COMMIT() asm volatile("cp.async.commit_group;" ::: "memory")
#define CP_WAIT1()  asm volatile("cp.async.wait_group 1;" ::: "memory")
#define CP_WAIT0()  asm volatile("cp.async.wait_group 0;" ::: "memory")

__device__ __forceinline__ void split2(float x, float y, uint32_t& hi, uint32_t& lo) {
    __nv_bfloat16 hx = __float2bfloat16(x), hy = __float2bfloat16(y);
    __nv_bfloat16 lx = __float2bfloat16(x - __bfloat162float(hx));
    __nv_bfloat16 ly = __float2bfloat16(y - __bfloat162float(hy));
    hi = ((uint32_t)__bfloat16_as_ushort(hy) << 16) | __bfloat16_as_ushort(hx);
    lo = ((uint32_t)__bfloat16_as_ushort(ly) << 16) | __bfloat16_as_ushort(lx);
}

// ============ prep kernels =================================================
__global__ void concat_split_kernel(const float4* __restrict__ x1,
                                    const float4* __restrict__ x2,
                                    __nv_bfloat16* __restrict__ xh,
                                    __nv_bfloat16* __restrict__ xl) {
    int idx = blockIdx.x * 256 + threadIdx.x;
    int p = idx & 255;
    int c = (idx >> 8) & 511;
    int b = idx >> 17;
    float4 v = (c < CH) ? x1[((b << 8) + c) * 256 + p]
                        : x2[((b << 8) + (c - CH)) * 256 + p];
    uint32_t h0, l0, h1, l1;
    split2(v.x, v.y, h0, l0);
    split2(v.z, v.w, h1, l1);
    *(uint2*)(xh + (size_t)idx * 4) = make_uint2(h0, h1);
    *(uint2*)(xl + (size_t)idx * 4) = make_uint2(l0, l1);
}

__global__ void fsplit_kernel(const float4* __restrict__ w,
                              __nv_bfloat16* __restrict__ wh,
                              __nv_bfloat16* __restrict__ wl) {
    int idx = blockIdx.x * 256 + threadIdx.x;
    float4 v = w[idx];
    uint32_t h0, l0, h1, l1;
    split2(v.x, v.y, h0, l0);
    split2(v.z, v.w, h1, l1);
    *(uint2*)(wh + (size_t)idx * 4) = make_uint2(h0, h1);
    *(uint2*)(wl + (size_t)idx * 4) = make_uint2(l0, l1);
}

// ============ winograd weight transform: U = G g G^T ======================
// thread per (co, ci); U[t][co][ci], ci fastest (coalesced writes)
__global__ void win_wt_kernel(const float* __restrict__ w,
                              __nv_bfloat16* __restrict__ uh,
                              __nv_bfloat16* __restrict__ ul) {
    int idx = blockIdx.x * 256 + threadIdx.x;   // 512*512
    int ci = idx & 511, co = idx >> 9;
    const float* g = w + ((long)co * CC + ci) * 9;
    float q[9];
#pragma unroll
    for (int i = 0; i < 9; i++) q[i] = g[i];
    // Gg : 4x3
    float t[4][3];
#pragma unroll
    for (int j = 0; j < 3; j++) {
        t[0][j] = q[0 * 3 + j];
        t[1][j] = 0.5f * (q[0 * 3 + j] + q[1 * 3 + j] + q[2 * 3 + j]);
        t[2][j] = 0.5f * (q[0 * 3 + j] - q[1 * 3 + j] + q[2 * 3 + j]);
        t[3][j] = q[2 * 3 + j];
    }
#pragma unroll
    for (int i = 0; i < 4; i++) {
        float u0 = t[i][0];
        float u1 = 0.5f * (t[i][0] + t[i][1] + t[i][2]);
        float u2 = 0.5f * (t[i][0] - t[i][1] + t[i][2]);
        float u3 = t[i][2];
        float uu[4] = {u0, u1, u2, u3};
#pragma unroll
        for (int j = 0; j < 4; j++) {
            float v = uu[j];
            __nv_bfloat16 h = __float2bfloat16(v);
            __nv_bfloat16 l = __float2bfloat16(v - __bfloat162float(h));
            long o = (((long)(i * 4 + j) * CC + co) << 9) + ci;
            uh[o] = h; ul[o] = l;
        }
    }
}

// ============ winograd input transform: V = B^T d B =======================
// thread per (b, ci, tile), tile fastest; V[b][t][ci][tile]
__global__ void win_in_kernel(const float* __restrict__ x1,
                              const float* __restrict__ x2,
                              __nv_bfloat16* __restrict__ vh,
                              __nv_bfloat16* __restrict__ vl) {
    int idx = blockIdx.x * 256 + threadIdx.x;   // 16*512*256
    int tile = idx & 255;
    int ci = (idx >> 8) & 511;
    int b = idx >> 17;
    int ty = tile >> 4, tx = tile & 15;
    const float* src = (ci < CH) ? (x1 + ((long)b * CH + ci) * HW)
                                 : (x2 + ((long)b * CH + (ci - CH)) * HW);
    float d[4][4];
#pragma unroll
    for (int r = 0; r < 4; r++) {
        int y = 2 * ty - 1 + r;
#pragma unroll
        for (int c = 0; c < 4; c++) {
            int x = 2 * tx - 1 + c;
            d[r][c] = ((unsigned)y < 32u && (unsigned)x < 32u)
                        ? src[(y << 5) + x] : 0.f;
        }
    }
    // column transform (B^T d)
    float m[4][4];
#pragma unroll
    for (int j = 0; j < 4; j++) {
        m[0][j] = d[0][j] - d[2][j];
        m[1][j] = d[1][j] + d[2][j];
        m[2][j] = d[2][j] - d[1][j];
        m[3][j] = d[1][j] - d[3][j];
    }
    // row transform ( · B )
#pragma unroll
    for (int i = 0; i < 4; i++) {
        float v0 = m[i][0] - m[i][2];
        float v1 = m[i][1] + m[i][2];
        float v2 = m[i][2] - m[i][1];
        float v3 = m[i][1] - m[i][3];
        float vv[4] = {v0, v1, v2, v3};
#pragma unroll
        for (int j = 0; j < 4; j++) {
            float v = vv[j];
            __nv_bfloat16 h = __float2bfloat16(v);
            __nv_bfloat16 l = __float2bfloat16(v - __bfloat162float(h));
            size_t o = ((((size_t)b * 16 + i * 4 + j) * CC + ci) << 8) + tile;
            vh[o] = h; vl[o] = l;
        }
    }
}

// ============ winograd output transform: Y = A^T M A, split for step 9 =====
// thread per (b, co, tile), tile fastest
__global__ void win_out_kernel(const float* __restrict__ M,
                               __nv_bfloat16* __restrict__ vh,
                               __nv_bfloat16* __restrict__ vl) {
    int idx = blockIdx.x * 256 + threadIdx.x;   // 16*512*256
    int tile = idx & 255;
    int co = (idx >> 8) & 511;
    int b = idx >> 17;
    int ty = tile >> 4, tx = tile & 15;
    float m[4][4];
#pragma unroll
    for (int t = 0; t < 16; t++)
        m[t >> 2][t & 3] = M[((((size_t)b * 16 + t) * CC + co) << 8) + tile];
    float p[2][4];
#pragma unroll
    for (int j = 0; j < 4; j++) {
        p[0][j] = m[0][j] + m[1][j] + m[2][j];
        p[1][j] = m[1][j] - m[2][j] - m[3][j];
    }
#pragma unroll
    for (int i = 0; i < 2; i++) {
        float y0 = p[i][0] + p[i][1] + p[i][2];
        float y1 = p[i][1] - p[i][2] - p[i][3];
        uint32_t h, l;
        split2(y0, y1, h, l);
        long o = ((((long)b * CC + co) << 10) + ((2 * ty + i) << 5) + 2 * tx);
        *(uint32_t*)(vh + o) = h;
        *(uint32_t*)(vl + o) = l;
    }
}

// ============ shared GEMM config ===========================================
#define KC       32
#define HTILE    8192
#define HSTAGE   (4 * HTILE)
#define HSTAGES  3
#define HDSMEM   (1024 + HSTAGES * HSTAGE)

#define MMA_CORE(AH, AL, BH, BL)                                               \
    _Pragma("unroll")                                                          \
    for (int am = 0; am < 4; am++)                                             \
        _Pragma("unroll")                                                      \
        for (int g = 0; g < 4; g++) {                                          \
            int bi = g >> 1, u = g & 1;                                        \
            MMA16816(acc[am][g], AH[am], BH[bi][u], BH[bi][u + 2]);            \
        }                                                                      \
    _Pragma("unroll")                                                          \
    for (int am = 0; am < 4; am++)                                             \
        _Pragma("unroll")                                                      \
        for (int g = 0; g < 4; g++) {                                          \
            int bi = g >> 1, u = g & 1;                                        \
            MMA16816(acc[am][g], AH[am], BL[bi][u], BL[bi][u + 2]);            \
        }                                                                      \
    _Pragma("unroll")                                                          \
    for (int am = 0; am < 4; am++)                                             \
        _Pragma("unroll")                                                      \
        for (int g = 0; g < 4; g++) {                                          \
            int bi = g >> 1, u = g & 1;                                        \
            MMA16816(acc[am][g], AL[am], BH[bi][u], BH[bi][u + 2]);            \
        }

// ============ generic HMMA GEMM ============================================
// NN=0: B [N][K] k-major. NN=1: B [K][N] rows (trans ldmatrix).
// EPI=0: fp32 out. EPI=1: bf16 hi/lo split out.
// A batch plane = (z & aMask) * sA  (aMask=-1: identity; conv-winograd: 15)
template<int NN, int EPI>
__global__ __launch_bounds__(256, 2)
void hmma_kernel(const __nv_bfloat16* __restrict__ Ahg,
                 const __nv_bfloat16* __restrict__ Alg,
                 const __nv_bfloat16* __restrict__ Bhg,
                 const __nv_bfloat16* __restrict__ Blg,
                 float* __restrict__ Cf,
                 __nv_bfloat16* __restrict__ Ch,
                 __nv_bfloat16* __restrict__ Cl,
                 int M, int N, int K, int aMask,
                 long sA, long sB, long sC, float alpha) {
    extern __shared__ char dsm_raw[];
    char* dsm = (char*)(((uintptr_t)dsm_raw + 1023) & ~(uintptr_t)1023);
    const uint32_t dsm_u32 = smem_to_u32(dsm);

    const int tid = threadIdx.x;
    const int wid = tid >> 5;
    const int lid = tid & 31;
    const int m0 = (wid >> 2) * 64;
    const int n0 = (wid & 3) * 32;
    const int bm = blockIdx.y * 128;
    const int bn = blockIdx.x * 128;
    const int b  = blockIdx.z;

    const __nv_bfloat16* Ah = Ahg + (long)(b & aMask) * sA;
    const __nv_bfloat16* Al = Alg + (long)(b & aMask) * sA;
    const __nv_bfloat16* Bh = Bhg + (long)b * sB;
    const __nv_bfloat16* Bl = Blg + (long)b * sB;

    const int frow = tid >> 1;
    const int fhalf = tid & 1;

    float acc[4][4][4];
#pragma unroll
    for (int i = 0; i < 4; i++)
#pragma unroll
        for (int j = 0; j < 4; j++)
#pragma unroll
            for (int q = 0; q < 4; q++) acc[i][j][q] = 0.f;

    auto prefetch = [&](int c, int st) {
        const uint32_t so = dsm_u32 + st * HSTAGE;
        const long kb = (long)c * KC + fhalf * 16;
        const __nv_bfloat16* pAh = Ah + (long)(bm + frow) * K + kb;
        const __nv_bfloat16* pAl = Al + (long)(bm + frow) * K + kb;
#pragma unroll
        for (int j = 0; j < 2; j++) {
            int chunk = fhalf * 2 + j;
            uint32_t off = frow * 64 + (((chunk ^ ((frow >> 1) & 3))) << 4);
            cp16(so + off,          pAh + j * 8);
            cp16(so + HTILE + off,  pAl + j * 8);
        }
        if (NN == 0) {
            const __nv_bfloat16* pBh = Bh + (long)(bn + frow) * K + kb;
            const __nv_bfloat16* pBl = Bl + (long)(bn + frow) * K + kb;
#pragma unroll
            for (int j = 0; j < 2; j++) {
                int chunk = fhalf * 2 + j;
                uint32_t off = frow * 64 + (((chunk ^ ((frow >> 1) & 3))) << 4);
                cp16(so + 2 * HTILE + off, pBh + j * 8);
                cp16(so + 3 * HTILE + off, pBl + j * 8);
            }
        } else {
#pragma unroll
            for (int j = 0; j < 2; j++) {
                int u = tid + 256 * j;
                int row = u >> 4;
                int ch  = u & 15;
                const long gb = (long)(c * KC + row) * N + bn + ch * 8;
                uint32_t off = row * 256 + (((ch ^ (row & 7))) << 4);
                cp16(so + 2 * HTILE + off, Bh + gb);
                cp16(so + 3 * HTILE + off, Bl + gb);
            }
        }
        CP_COMMIT();
    };

    const int rsel = lid & 15, csel = lid >> 4;
    auto mma_step = [&](int st, int s) {
        const uint32_t base = dsm_u32 + st * HSTAGE;
        uint32_t ah[4][4], al[4][4], bh2[2][4], bl2[2][4];
#pragma unroll
        for (int am = 0; am < 4; am++) {
            int row = m0 + am * 16 + rsel;
            uint32_t off = row * 64 + ((((2 * s + csel) ^ ((row >> 1) & 3))) << 4);
            LDSM_X4(ah[am], base + off);
            LDSM_X4(al[am], base + HTILE + off);
        }
        if (NN == 0) {
#pragma unroll
            for (int bi = 0; bi < 2; bi++) {
                int row = n0 + bi * 16 + rsel;
                uint32_t off = row * 64 + ((((2 * s + csel) ^ ((row >> 1) & 3))) << 4);
                LDSM_X4(bh2[bi], base + 2 * HTILE + off);
                LDSM_X4(bl2[bi], base + 3 * HTILE + off);
            }
        } else {
            int krow = s * 16 + ((lid >> 4) << 3) + (lid & 7);
#pragma unroll
            for (int bi = 0; bi < 2; bi++) {
                int nch = (n0 >> 3) + bi * 2 + ((lid >> 3) & 1);
                uint32_t off = krow * 256 + (((nch ^ (krow & 7))) << 4);
                LDSM_X4_T(bh2[bi], base + 2 * HTILE + off);
                LDSM_X4_T(bl2[bi], base + 3 * HTILE + off);
            }
        }
        MMA_CORE(ah, al, bh2, bl2)
    };

    const int nch = K / KC;
    prefetch(0, 0);
    prefetch(1, 1);
    int st = 0;
    for (int c = 0; c < nch; c++) {
        if (c + 2 < nch) CP_WAIT1(); else CP_WAIT0();
        __syncthreads();
        mma_step(st, 0);
        mma_step(st, 1);
        if (c + 2 < nch) prefetch(c + 2, (st + 2) % HSTAGES);
        st = (st + 1 == HSTAGES) ? 0 : st + 1;
    }

    const int rg = lid >> 2;
    const int cg = (lid & 3) * 2;
#pragma unroll
    for (int am = 0; am < 4; am++)
#pragma unroll
        for (int g = 0; g < 4; g++) {
            int row = bm + m0 + am * 16 + rg;
            int col = bn + n0 + g * 8 + cg;
            float v0 = alpha * acc[am][g][0], v1 = alpha * acc[am][g][1];
            float v2 = alpha * acc[am][g][2], v3 = alpha * acc[am][g][3];
            if (EPI == 0) {
                float* p0 = Cf + (long)b * sC + (long)row * N + col;
                *(float2*)p0 = make_float2(v0, v1);
                *(float2*)(p0 + (long)8 * N) = make_float2(v2, v3);
            } else {
                uint32_t h, l;
                long o0 = (long)b * sC + (long)row * N + col;
                long o1 = o0 + (long)8 * N;
                split2(v0, v1, h, l);
                *(uint32_t*)(Ch + o0) = h; *(uint32_t*)(Cl + o0) = l;
                split2(v2, v3, h, l);
                *(uint32_t*)(Ch + o1) = h; *(uint32_t*)(Cl + o1) = l;
            }
        }
}

// ---------------- random_map = weight1 @ weight2^T -------------------------
__global__ void rmap_kernel(const float* __restrict__ w1,
                            const float* __restrict__ w2,
                            float* __restrict__ rm) {
    int idx = blockIdx.x * 256 + threadIdx.x;
    int i = idx >> 9, j = idx & 511;
    float s = 0.f;
#pragma unroll
    for (int k = 0; k < 16; k++) s += w1[i * 16 + k] * w2[j * 16 + k];
    rm[idx] = s;
}

// ---------------- softmax over 512 + rmap; writes bf16 hi/lo rows ----------
__global__ void softmax_kernel(const float* __restrict__ S,
                               const float* __restrict__ rmap,
                               __nv_bfloat16* __restrict__ oh,
                               __nv_bfloat16* __restrict__ ol) {
    const int c = blockIdx.x, b = blockIdx.y;
    const float* row = S + ((long)b * CC + c) * CC;
    const float* rm = rmap + (long)c * CC;
    const int t = threadIdx.x;
    __shared__ float smax[4], ssum[4];
    float v[4];
#pragma unroll
    for (int j = 0; j < 4; j++) v[j] = row[t + 128 * j] + rm[t + 128 * j];
    float m = fmaxf(fmaxf(v[0], v[1]), fmaxf(v[2], v[3]));
    for (int o = 16; o; o >>= 1) m = fmaxf(m, __shfl_xor_sync(0xffffffffu, m, o));
    if ((t & 31) == 0) smax[t >> 5] = m;
    __syncthreads();
    m = fmaxf(fmaxf(smax[0], smax[1]), fmaxf(smax[2], smax[3]));
    float e[4], s = 0.f;
#pragma unroll
    for (int j = 0; j < 4; j++) { e[j] = __expf(v[j] - m); s += e[j]; }
    for (int o = 16; o; o >>= 1) s += __shfl_xor_sync(0xffffffffu, s, o);
    if ((t & 31) == 0) ssum[t >> 5] = s;
    __syncthreads();
    s = ssum[0] + ssum[1] + ssum[2] + ssum[3];
    float inv = 1.0f / s;
    __nv_bfloat16* ph = oh + ((long)b * CC + c) * CC;
    __nv_bfloat16* pl = ol + ((long)b * CC + c) * CC;
#pragma unroll
    for (int j = 0; j < 4; j++) {
        float x = e[j] * inv;
        __nv_bfloat16 h = __float2bfloat16(x);
        __nv_bfloat16 l = __float2bfloat16(x - __bfloat162float(h));
        ph[t + 128 * j] = h; pl[t + 128 * j] = l;
    }
}

// ---------------- launch ---------------------------------------------------
extern "C" void kernel_launch(void* const* d_in, const int* in_sizes, int n_in,
                              void* d_out, int out_size) {
    const float* x1  = (const float*)d_in[0];
    const float* x2  = (const float*)d_in[1];
    const float* g_w = (const float*)d_in[2];
    const float* w_w = (const float*)d_in[3];
    const float* w1  = (const float*)d_in[4];
    const float* w2  = (const float*)d_in[5];
    float* out = (float*)d_out;

    __nv_bfloat16 *xh, *xl, *uh, *ul, *vwh, *vwl, *vh, *vl;
    __nv_bfloat16 *ah, *al, *th, *tl, *wwh, *wwl;
    float *attn, *rmap, *Mbuf;
    cudaGetSymbolAddress((void**)&xh, g_xh);
    cudaGetSymbolAddress((void**)&xl, g_xl);
    cudaGetSymbolAddress((void**)&uh, g_uh);
    cudaGetSymbolAddress((void**)&ul, g_ul);
    cudaGetSymbolAddress((void**)&vwh, g_vwh);
    cudaGetSymbolAddress((void**)&vwl, g_vwl);
    cudaGetSymbolAddress((void**)&Mbuf, g_m);
    cudaGetSymbolAddress((void**)&vh, g_vh);
    cudaGetSymbolAddress((void**)&vl, g_vl);
    cudaGetSymbolAddress((void**)&ah, g_ah);
    cudaGetSymbolAddress((void**)&al, g_al);
    cudaGetSymbolAddress((void**)&th, g_th);
    cudaGetSymbolAddress((void**)&tl, g_tl);
    cudaGetSymbolAddress((void**)&wwh, g_wwh);
    cudaGetSymbolAddress((void**)&wwl, g_wwl);
    cudaGetSymbolAddress((void**)&attn, g_attn);
    cudaGetSymbolAddress((void**)&rmap, g_rmap);

    cudaFuncSetAttribute(hmma_kernel<0, 0>,
                         cudaFuncAttributeMaxDynamicSharedMemorySize, HDSMEM);
    cudaFuncSetAttribute(hmma_kernel<1, 0>,
                         cudaFuncAttributeMaxDynamicSharedMemorySize, HDSMEM);
    cudaFuncSetAttribute(hmma_kernel<1, 1>,
                         cudaFuncAttributeMaxDynamicSharedMemorySize, HDSMEM);

    // 1. concat + split -> X (for sim)
    concat_split_kernel<<<BATCH * CC * 256 / 256, 256>>>(
        (const float4*)x1, (const float4*)x2, xh, xl);

    // 2. winograd input transform: V[b][t][ci][tile]
    win_in_kernel<<<(BATCH * CC * NTILE) / 256, 256>>>(x1, x2, vwh, vwl);

    // 3. winograd weight transform: U[t][co][ci]
    win_wt_kernel<<<(CC * CC) / 256, 256>>>(g_w, uh, ul);

    // 4. winograd GEMM: M[z=(b,t)] = U[t] @ V[b][t]  (NN, fp32 out)
    {
        dim3 grid(NTILE / 128, CC / 128, BATCH * 16);   // (2, 4, 256)
        hmma_kernel<1, 0><<<grid, 256, HDSMEM>>>(
            uh, ul, vwh, vwl, Mbuf, nullptr, nullptr,
            CC, NTILE, CC, 15,
            (long)CC * CC, (long)CC * NTILE, (long)CC * NTILE, 1.0f);
    }

    // 5. winograd output transform -> value bf16 hi/lo rows
    win_out_kernel<<<(BATCH * CC * NTILE) / 256, 256>>>(Mbuf, vh, vl);

    // 6. w_w split, random_map
    fsplit_kernel<<<(CO * CC / 4) / 256, 256>>>((const float4*)w_w, wwh, wwl);
    rmap_kernel<<<(CC * CC) / 256, 256>>>(w1, w2, rmap);

    // 7. sim = (q @ q^T) * c^-0.5  (NT, fp32 out)
    {
        dim3 grid(CC / 128, CC / 128, BATCH);
        hmma_kernel<0, 0><<<grid, 256, HDSMEM>>>(
            xh, xl, xh, xl, attn, nullptr, nullptr,
            CC, CC, HW, 0x7FFFFFFF,
            (long)CC * HW, (long)CC * HW, (long)CC * CC,
            1.0f / sqrtf((float)CC));
    }

    // 8. softmax(sim + rmap) -> attn bf16 hi/lo rows
    {
        dim3 grid(CC, BATCH);
        softmax_kernel<<<grid, 128>>>(attn, rmap, ah, al);
    }

    // 9. T = w_w @ attn  (NN, bf16-split out)
    {
        dim3 grid(CC / 128, CO / 128, BATCH);
        hmma_kernel<1, 1><<<grid, 256, HDSMEM>>>(
            wwh, wwl, ah, al, nullptr, th, tl,
            CO, CC, CC, 0,
            0L, (long)CC * CC, (long)CO * CC, 1.0f);
    }

    // 10. out = T @ value  (NN, fp32 out)
    {
        dim3 grid(HW / 128, CO / 128, BATCH);
        hmma_kernel<1, 0><<<grid, 256, HDSMEM>>>(
            th, tl, vh, vl, out, nullptr, nullptr,
            CO, HW, CC, 0x7FFFFFFF,
            (long)CO * CC, (long)CC * HW, (long)CO * HW, 1.0f);
    }
}